// round 12
// baseline (speedup 1.0000x reference)
#include <cuda_runtime.h>
#include <cuda_fp16.h>
#include <math.h>

#define NV 3
#define NB 2
#define NC 64
#define NSC 32
#define NH 128
#define NW 128
#define HW (NH*NW)
#define PW 131                      // padded width  (1 left, 2 right)
#define PH 131                      // padded height (1 top, 2 bottom)
#define PP (PW*PH)
#define PIX_PER_BLK 32              // 256 threads, 8 lanes per pixel
#define GRIDX (HW/PIX_PER_BLK)      // 512

// Allocation-free scratch (zero-initialized; padding ring of g_fht stays 0).
__device__ float g_proj[(NV-1)*NB][12];
__device__ float g_partial[NB*NSC*GRIDX];
__device__ __align__(16) __half2 g_fht[(size_t)NV*NB*PP*(NC/2)];
// Tap records: per (b,s,pix,view): {base_off(uint4 units), pack(w0,w1), pack(w2,w3), 0}
__device__ __align__(16) uint4 g_rec[(size_t)NB*NSC*HW*2];

__device__ __forceinline__ void mat3mul(const float* A, const float* B, float* C) {
    #pragma unroll
    for (int i = 0; i < 3; i++)
        #pragma unroll
        for (int j = 0; j < 3; j++)
            C[i*3+j] = A[i*3+0]*B[0*3+j] + A[i*3+1]*B[1*3+j] + A[i*3+2]*B[2*3+j];
}
__device__ __forceinline__ void mat3vec(const float* A, const float* v, float* r) {
    #pragma unroll
    for (int i = 0; i < 3; i++)
        r[i] = A[i*3+0]*v[0] + A[i*3+1]*v[1] + A[i*3+2]*v[2];
}
__device__ __forceinline__ void mat3inv(const float* A, float* Ai) {
    float a=A[0],b=A[1],c=A[2],d=A[3],e=A[4],f=A[5],g=A[6],h=A[7],i=A[8];
    float det = a*(e*i-f*h) - b*(d*i-f*g) + c*(d*h-e*g);
    float inv = 1.0f / det;
    Ai[0] =  (e*i - f*h)*inv; Ai[1] = -(b*i - c*h)*inv; Ai[2] =  (b*f - c*e)*inv;
    Ai[3] = -(d*i - f*g)*inv; Ai[4] =  (a*i - c*g)*inv; Ai[5] = -(a*f - c*d)*inv;
    Ai[6] =  (d*h - e*g)*inv; Ai[7] = -(a*h - b*g)*inv; Ai[8] =  (a*e - b*d)*inv;
}
__device__ __forceinline__ __half2 u2h2(unsigned u) {
    return *reinterpret_cast<__half2*>(&u);
}
__device__ __forceinline__ unsigned packh2(__half a, __half b) {
    __half2 h = __halves2half2(a, b);
    return *reinterpret_cast<unsigned*>(&h);
}

// ---------------------------------------------------------------------------
// Transpose (C,HW) -> padded (PH,PW,C) fp16 (vectorized); homography prep
// fused into block (0,0).  grid (HW/32, V*B), 256 threads.
// ---------------------------------------------------------------------------
__global__ void __launch_bounds__(256) k_tr(const float* __restrict__ feat,
                                            const float* __restrict__ intr,
                                            const float* __restrict__ c2w) {
    if (blockIdx.x == 0 && blockIdx.y == 0 && threadIdx.x < (NV-1)*NB) {
        int tid = threadIdx.x;
        int v = 1 + tid / NB;
        int b = tid % NB;
        const float* Kr = intr + (0*NB + b)*9;
        const float* Tr = c2w  + (0*NB + b)*16;
        const float* Ks = intr + (v*NB + b)*9;
        const float* Ts = c2w  + (v*NB + b)*16;

        float RrT[9], RsT[9], tr[3], ts[3];
        #pragma unroll
        for (int i = 0; i < 3; i++) {
            #pragma unroll
            for (int j = 0; j < 3; j++) {
                RrT[j*3+i] = Tr[i*4+j];
                RsT[j*3+i] = Ts[i*4+j];
            }
            tr[i] = Tr[i*4+3];
            ts[i] = Ts[i*4+3];
        }
        float trw[3], tsw[3], tmp[3];
        mat3vec(RrT, tr, tmp); trw[0]=-tmp[0]; trw[1]=-tmp[1]; trw[2]=-tmp[2];
        mat3vec(RsT, ts, tmp); tsw[0]=-tmp[0]; tsw[1]=-tmp[1]; tsw[2]=-tmp[2];

        float A[9], bref[3], Ai[9];
        mat3mul(Kr, RrT, A);
        mat3vec(Kr, trw, tmp);
        bref[0]=tmp[0]+trw[0]; bref[1]=tmp[1]+trw[1]; bref[2]=tmp[2]+trw[2];
        mat3inv(A, Ai);

        float SM[9], St[3];
        mat3mul(Ks, RsT, SM);
        mat3vec(Ks, tsw, tmp);
        St[0]=tmp[0]+tsw[0]; St[1]=tmp[1]+tsw[1]; St[2]=tmp[2]+tsw[2];

        float M[9], Mb[3];
        mat3mul(SM, Ai, M);
        mat3vec(M, bref, Mb);

        float* o = g_proj[(v-1)*NB + b];
        #pragma unroll
        for (int i = 0; i < 9; i++) o[i] = M[i];
        o[9]  = St[0] - Mb[0];
        o[10] = St[1] - Mb[1];
        o[11] = St[2] - Mb[2];
    }

    __shared__ float t[NC][33];
    const int vb  = blockIdx.y;
    const int hw0 = blockIdx.x * 32;
    const int tid = threadIdx.x;
    const float* src = feat + (size_t)vb * NC * HW;

    #pragma unroll
    for (int i = tid; i < NC*8; i += 256) {
        int c = i >> 3, j4 = (i & 7) << 2;
        float4 v4 = *(const float4*)(src + (size_t)c * HW + hw0 + j4);
        t[c][j4+0] = v4.x; t[c][j4+1] = v4.y; t[c][j4+2] = v4.z; t[c][j4+3] = v4.w;
    }
    __syncthreads();

    {
        int pg = tid >> 3;           // pixel 0..31
        int g8 = tid & 7;            // channel-group of 8
        int g  = hw0 + pg;
        int y  = g >> 7, x = g & 127;
        uint4 o4;
        unsigned* op = &o4.x;
        #pragma unroll
        for (int k = 0; k < 4; k++) {
            __half2 h = __floats2half2_rn(t[g8*8 + 2*k][pg], t[g8*8 + 2*k + 1][pg]);
            op[k] = *reinterpret_cast<unsigned*>(&h);
        }
        uint4* dst = (uint4*)(g_fht + (size_t)vb * PP * (NC/2));
        dst[(size_t)((y+1)*PW + (x+1)) * 8 + g8] = o4;
    }
}

// ---------------------------------------------------------------------------
// Tap-record precompute. grid (HW/256, NSC, NB), 256 threads.
// ---------------------------------------------------------------------------
__global__ void __launch_bounds__(256) k_setup(const float* __restrict__ scale_hypo,
                                              const float* __restrict__ depth_init) {
    const int pix = blockIdx.x * 256 + threadIdx.x;
    const int s   = blockIdx.y;
    const int b   = blockIdx.z;
    const float fx = (float)(pix & (NW-1));
    const float fy = (float)(pix >> 7);

    const float d = depth_init[b*HW + pix] * scale_hypo[b*NSC + s];
    const float CX = (float)NW / (float)(NW-1);
    const float CY = (float)NH / (float)(NH-1);

    uint4* recp = g_rec + ((size_t)(b*NSC + s)*HW + pix)*2;

    #pragma unroll
    for (int vv = 0; vv < 2; vv++) {
        const float* P = g_proj[vv*NB + b];
        float m0 = P[0]*fx + P[1]*fy + P[2];
        float m1 = P[3]*fx + P[4]*fy + P[5];
        float m2 = P[6]*fx + P[7]*fy + P[8];
        float px = fmaf(m0, d, P[9]);
        float py = fmaf(m1, d, P[10]);
        float pz = fmaf(m2, d, P[11]);
        float rz = __fdividef(1.0f, pz);
        float ix = fmaf(px*rz, CX, -0.5f);
        float iy = fmaf(py*rz, CY, -0.5f);
        ix = fminf(fmaxf(ix, -1.0f), (float)NW);
        iy = fminf(fmaxf(iy, -1.0f), (float)NH);
        float x0f = floorf(ix), y0f = floorf(iy);
        float wx1 = ix - x0f, wx0 = 1.0f - wx1;
        float wy1 = iy - y0f, wy0 = 1.0f - wy1;
        int x0p = (int)x0f + 1;
        int y0p = (int)y0f + 1;
        uint4 rec;
        rec.x = (unsigned)((y0p*PW + x0p) << 3);
        rec.y = packh2(__float2half_rn(wx0*wy0), __float2half_rn(wx1*wy0));
        rec.z = packh2(__float2half_rn(wx0*wy1), __float2half_rn(wx1*wy1));
        rec.w = 0;
        recp[vv] = rec;
    }
}

// ---------------------------------------------------------------------------
// Main gather kernel. 256 threads = 32 pixels x 8 channel-lanes.
// ALL records for the block staged to smem up front (bulk coalesced loads),
// removing the per-scale L2 record-load dependency chain from the hot loop.
// ---------------------------------------------------------------------------
__global__ void __launch_bounds__(256) k_main() {
    const int b    = blockIdx.y;
    const int tid  = threadIdx.x;
    const int w    = tid >> 5;             // warp 0..7
    const int l    = tid & 31;
    const int pg   = (w << 2) | (l >> 3);  // pixel in block 0..31
    const int cl   = l & 7;                // channel chunk 0..7
    const int pix0 = blockIdx.x * PIX_PER_BLK;
    const int pix  = pix0 + pg;

    __shared__ __align__(16) uint4 s_rec[NSC][2*PIX_PER_BLK];  // 32 KB
    __shared__ float s_part[NSC][8];

    // ---- stage all 2048 records (fully coalesced, 8 per thread) ----
    {
        const uint4* grp = g_rec + ((size_t)(b*NSC)*HW + pix0)*2;
        #pragma unroll
        for (int i = 0; i < 8; i++) {
            int idx = i*256 + tid;
            int ss  = idx >> 6;          // scale
            int j   = idx & 63;          // record within scale (pix*2+view)
            s_rec[ss][j] = grp[(size_t)ss*HW*2 + j];
        }
    }

    const uint4* f0 = (const uint4*)(g_fht + (size_t)(0*NB + b)*PP*(NC/2)) + cl;
    const uint4* f1 = (const uint4*)(g_fht + (size_t)(1*NB + b)*PP*(NC/2)) + cl;
    const uint4* f2 = (const uint4*)(g_fht + (size_t)(2*NB + b)*PP*(NC/2)) + cl;

    __half2 r0h[4];
    {
        int pixp = ((pix >> 7) + 1)*PW + (pix & 127) + 1;
        uint4 q = f0[pixp << 3];
        r0h[0] = u2h2(q.x); r0h[1] = u2h2(q.y);
        r0h[2] = u2h2(q.z); r0h[3] = u2h2(q.w);
    }

    __syncthreads();   // records staged

    #pragma unroll 1
    for (int s = 0; s < NSC; s++) {
        uint4 ra = s_rec[s][pg*2 + 0];   // broadcast LDS (8 lanes same addr)
        uint4 rb = s_rec[s][pg*2 + 1];
        const int o1 = (int)ra.x;
        const int o2 = (int)rb.x;

        const __half2 zero = __float2half2_rn(0.0f);
        __half2 w1lo = u2h2(ra.y);
        __half2 w1hi = u2h2(ra.z);
        __half2 w2lo = u2h2(rb.y);
        __half2 w2hi = u2h2(rb.z);

        // view 1 (4 taps)
        __half2 s1[4] = {zero, zero, zero, zero};
        {
            uint4 q; __half2 ww;
            q = f1[o1];               ww = __low2half2(w1lo);
            s1[0]=__hfma2(u2h2(q.x),ww,s1[0]); s1[1]=__hfma2(u2h2(q.y),ww,s1[1]);
            s1[2]=__hfma2(u2h2(q.z),ww,s1[2]); s1[3]=__hfma2(u2h2(q.w),ww,s1[3]);
            q = f1[o1 + 8];           ww = __high2half2(w1lo);
            s1[0]=__hfma2(u2h2(q.x),ww,s1[0]); s1[1]=__hfma2(u2h2(q.y),ww,s1[1]);
            s1[2]=__hfma2(u2h2(q.z),ww,s1[2]); s1[3]=__hfma2(u2h2(q.w),ww,s1[3]);
            q = f1[o1 + (PW<<3)];     ww = __low2half2(w1hi);
            s1[0]=__hfma2(u2h2(q.x),ww,s1[0]); s1[1]=__hfma2(u2h2(q.y),ww,s1[1]);
            s1[2]=__hfma2(u2h2(q.z),ww,s1[2]); s1[3]=__hfma2(u2h2(q.w),ww,s1[3]);
            q = f1[o1 + (PW<<3) + 8]; ww = __high2half2(w1hi);
            s1[0]=__hfma2(u2h2(q.x),ww,s1[0]); s1[1]=__hfma2(u2h2(q.y),ww,s1[1]);
            s1[2]=__hfma2(u2h2(q.z),ww,s1[2]); s1[3]=__hfma2(u2h2(q.w),ww,s1[3]);
        }
        __half2 r1h[4];
        __half2 acc1h = zero;
        #pragma unroll
        for (int c = 0; c < 4; c++) {
            r1h[c] = __hsub2(r0h[c], s1[c]);
            acc1h = __hfma2(r1h[c], r1h[c], acc1h);
        }

        // view 2 (4 taps)
        __half2 s2[4] = {zero, zero, zero, zero};
        {
            uint4 q; __half2 ww;
            q = f2[o2];               ww = __low2half2(w2lo);
            s2[0]=__hfma2(u2h2(q.x),ww,s2[0]); s2[1]=__hfma2(u2h2(q.y),ww,s2[1]);
            s2[2]=__hfma2(u2h2(q.z),ww,s2[2]); s2[3]=__hfma2(u2h2(q.w),ww,s2[3]);
            q = f2[o2 + 8];           ww = __high2half2(w2lo);
            s2[0]=__hfma2(u2h2(q.x),ww,s2[0]); s2[1]=__hfma2(u2h2(q.y),ww,s2[1]);
            s2[2]=__hfma2(u2h2(q.z),ww,s2[2]); s2[3]=__hfma2(u2h2(q.w),ww,s2[3]);
            q = f2[o2 + (PW<<3)];     ww = __low2half2(w2hi);
            s2[0]=__hfma2(u2h2(q.x),ww,s2[0]); s2[1]=__hfma2(u2h2(q.y),ww,s2[1]);
            s2[2]=__hfma2(u2h2(q.z),ww,s2[2]); s2[3]=__hfma2(u2h2(q.w),ww,s2[3]);
            q = f2[o2 + (PW<<3) + 8]; ww = __high2half2(w2hi);
            s2[0]=__hfma2(u2h2(q.x),ww,s2[0]); s2[1]=__hfma2(u2h2(q.y),ww,s2[1]);
            s2[2]=__hfma2(u2h2(q.z),ww,s2[2]); s2[3]=__hfma2(u2h2(q.w),ww,s2[3]);
        }
        __half2 acc2h = zero;
        #pragma unroll
        for (int c = 0; c < 4; c++) {
            __half2 r2 = __hsub2(r1h[c], s2[c]);
            acc2h = __hfma2(r2, r2, acc2h);
        }

        float2 a1 = __half22float2(acc1h);
        float2 a2 = __half22float2(acc2h);
        float acc1 = a1.x + a1.y;
        float acc2 = a2.x + a2.y;

        #pragma unroll
        for (int o = 4; o > 0; o >>= 1) {
            acc1 += __shfl_xor_sync(0xffffffffu, acc1, o);
            acc2 += __shfl_xor_sync(0xffffffffu, acc2, o);
        }
        float cst = sqrtf(acc1) + sqrtf(acc2);
        cst += __shfl_xor_sync(0xffffffffu, cst, 8);
        cst += __shfl_xor_sync(0xffffffffu, cst, 16);
        if (l == 0) s_part[s][w] = cst;
    }

    __syncthreads();
    if (tid < NSC) {
        float v = 0.0f;
        #pragma unroll
        for (int i = 0; i < 8; i++) v += s_part[tid][i];
        g_partial[(b*NSC + tid)*GRIDX + blockIdx.x] = v;
    }
}

// ---------------------------------------------------------------------------
// Fused reduce + softmax. grid = NB, 1024 threads.
// ---------------------------------------------------------------------------
__global__ void __launch_bounds__(1024) k_redfin(const float* __restrict__ scale_hypo,
                                                float* __restrict__ out) {
    const int b    = blockIdx.x;
    const int wid  = threadIdx.x >> 5;
    const int lane = threadIdx.x & 31;

    const float4* p = (const float4*)(g_partial + (b*NSC + wid)*GRIDX);
    float v = 0.0f;
    #pragma unroll
    for (int i = 0; i < 4; i++) {
        float4 t = p[lane + 32*i];
        v += t.x + t.y + t.z + t.w;
    }
    #pragma unroll
    for (int o = 16; o > 0; o >>= 1)
        v += __shfl_xor_sync(0xffffffffu, v, o);

    __shared__ float sc[NSC];
    if (lane == 0) sc[wid] = v * (1.0f / (2.0f * (float)HW));
    __syncthreads();

    if (wid == 0) {
        float cost = sc[lane];
        float m = cost;
        #pragma unroll
        for (int o = 16; o > 0; o >>= 1)
            m = fmaxf(m, __shfl_xor_sync(0xffffffffu, m, o));
        float e = expf(cost - m);
        float shp = scale_hypo[b*NSC + lane];
        float den = e, num = e * shp;
        #pragma unroll
        for (int o = 16; o > 0; o >>= 1) {
            den += __shfl_xor_sync(0xffffffffu, den, o);
            num += __shfl_xor_sync(0xffffffffu, num, o);
        }
        if (lane == 0) out[b] = num / den;
    }
}

extern "C" void kernel_launch(void* const* d_in, const int* in_sizes, int n_in,
                              void* d_out, int out_size) {
    const float* feat  = (const float*)d_in[0];
    const float* intr  = (const float*)d_in[1];
    const float* c2w   = (const float*)d_in[2];
    const float* scale = (const float*)d_in[3];
    const float* depth = (const float*)d_in[4];
    float* out = (float*)d_out;

    dim3 trg(HW/32, NV*NB);
    k_tr<<<trg, 256>>>(feat, intr, c2w);
    dim3 sg(HW/256, NSC, NB);
    k_setup<<<sg, 256>>>(scale, depth);
    dim3 grid(GRIDX, NB);
    k_main<<<grid, 256>>>();
    k_redfin<<<NB, 1024>>>(scale, out);
}

// round 13
// speedup vs baseline: 1.0940x; 1.0940x over previous
#include <cuda_runtime.h>
#include <cuda_fp16.h>
#include <math.h>

#define NV 3
#define NB 2
#define NC 64
#define NSC 32
#define NH 128
#define NW 128
#define HW (NH*NW)
#define PW 131                      // padded width  (1 left, 2 right)
#define PH 131                      // padded height (1 top, 2 bottom)
#define PP (PW*PH)
#define PIX_PER_BLK 32
#define GRIDX (HW/PIX_PER_BLK)      // 512

// Allocation-free scratch (zero-initialized; padding ring of g_fht stays 0).
__device__ float g_proj[(NV-1)*NB][12];
__device__ float g_partial[NB*NSC*GRIDX];
__device__ __align__(16) __half2 g_fht[(size_t)NV*NB*PP*(NC/2)];
// Tap records: per (b,s,pix,view): {base_off(uint4 units), pack(w0,w1), pack(w2,w3), 0}
__device__ __align__(16) uint4 g_rec[(size_t)NB*NSC*HW*2];

__device__ __forceinline__ void mat3mul(const float* A, const float* B, float* C) {
    #pragma unroll
    for (int i = 0; i < 3; i++)
        #pragma unroll
        for (int j = 0; j < 3; j++)
            C[i*3+j] = A[i*3+0]*B[0*3+j] + A[i*3+1]*B[1*3+j] + A[i*3+2]*B[2*3+j];
}
__device__ __forceinline__ void mat3vec(const float* A, const float* v, float* r) {
    #pragma unroll
    for (int i = 0; i < 3; i++)
        r[i] = A[i*3+0]*v[0] + A[i*3+1]*v[1] + A[i*3+2]*v[2];
}
__device__ __forceinline__ void mat3inv(const float* A, float* Ai) {
    float a=A[0],b=A[1],c=A[2],d=A[3],e=A[4],f=A[5],g=A[6],h=A[7],i=A[8];
    float det = a*(e*i-f*h) - b*(d*i-f*g) + c*(d*h-e*g);
    float inv = 1.0f / det;
    Ai[0] =  (e*i - f*h)*inv; Ai[1] = -(b*i - c*h)*inv; Ai[2] =  (b*f - c*e)*inv;
    Ai[3] = -(d*i - f*g)*inv; Ai[4] =  (a*i - c*g)*inv; Ai[5] = -(a*f - c*d)*inv;
    Ai[6] =  (d*h - e*g)*inv; Ai[7] = -(a*h - b*g)*inv; Ai[8] =  (a*e - b*d)*inv;
}
__device__ __forceinline__ __half2 u2h2(unsigned u) {
    return *reinterpret_cast<__half2*>(&u);
}
__device__ __forceinline__ unsigned packh2(__half a, __half b) {
    __half2 h = __halves2half2(a, b);
    return *reinterpret_cast<unsigned*>(&h);
}

// ---------------------------------------------------------------------------
// Transpose (C,HW) -> padded (PH,PW,C) fp16 (vectorized, from R8); homography
// prep fused into block (0,0).  grid (HW/32, V*B), 256 threads.
// ---------------------------------------------------------------------------
__global__ void __launch_bounds__(256) k_tr(const float* __restrict__ feat,
                                            const float* __restrict__ intr,
                                            const float* __restrict__ c2w) {
    if (blockIdx.x == 0 && blockIdx.y == 0 && threadIdx.x < (NV-1)*NB) {
        int tid = threadIdx.x;
        int v = 1 + tid / NB;
        int b = tid % NB;
        const float* Kr = intr + (0*NB + b)*9;
        const float* Tr = c2w  + (0*NB + b)*16;
        const float* Ks = intr + (v*NB + b)*9;
        const float* Ts = c2w  + (v*NB + b)*16;

        float RrT[9], RsT[9], tr[3], ts[3];
        #pragma unroll
        for (int i = 0; i < 3; i++) {
            #pragma unroll
            for (int j = 0; j < 3; j++) {
                RrT[j*3+i] = Tr[i*4+j];
                RsT[j*3+i] = Ts[i*4+j];
            }
            tr[i] = Tr[i*4+3];
            ts[i] = Ts[i*4+3];
        }
        float trw[3], tsw[3], tmp[3];
        mat3vec(RrT, tr, tmp); trw[0]=-tmp[0]; trw[1]=-tmp[1]; trw[2]=-tmp[2];
        mat3vec(RsT, ts, tmp); tsw[0]=-tmp[0]; tsw[1]=-tmp[1]; tsw[2]=-tmp[2];

        float A[9], bref[3], Ai[9];
        mat3mul(Kr, RrT, A);
        mat3vec(Kr, trw, tmp);
        bref[0]=tmp[0]+trw[0]; bref[1]=tmp[1]+trw[1]; bref[2]=tmp[2]+trw[2];
        mat3inv(A, Ai);

        float SM[9], St[3];
        mat3mul(Ks, RsT, SM);
        mat3vec(Ks, tsw, tmp);
        St[0]=tmp[0]+tsw[0]; St[1]=tmp[1]+tsw[1]; St[2]=tmp[2]+tsw[2];

        float M[9], Mb[3];
        mat3mul(SM, Ai, M);
        mat3vec(M, bref, Mb);

        float* o = g_proj[(v-1)*NB + b];
        #pragma unroll
        for (int i = 0; i < 9; i++) o[i] = M[i];
        o[9]  = St[0] - Mb[0];
        o[10] = St[1] - Mb[1];
        o[11] = St[2] - Mb[2];
    }

    __shared__ float t[NC][33];
    const int vb  = blockIdx.y;
    const int hw0 = blockIdx.x * 32;
    const int tid = threadIdx.x;
    const float* src = feat + (size_t)vb * NC * HW;

    // vectorized read: 512 float4 loads (2 per thread)
    #pragma unroll
    for (int i = tid; i < NC*8; i += 256) {
        int c = i >> 3, j4 = (i & 7) << 2;
        float4 v4 = *(const float4*)(src + (size_t)c * HW + hw0 + j4);
        t[c][j4+0] = v4.x; t[c][j4+1] = v4.y; t[c][j4+2] = v4.z; t[c][j4+3] = v4.w;
    }
    __syncthreads();

    // vectorized write: one uint4 (8 channels) per thread
    {
        int pg = tid >> 3;           // pixel 0..31
        int g8 = tid & 7;            // channel-group of 8
        int g  = hw0 + pg;
        int y  = g >> 7, x = g & 127;
        uint4 o4;
        unsigned* op = &o4.x;
        #pragma unroll
        for (int k = 0; k < 4; k++) {
            __half2 h = __floats2half2_rn(t[g8*8 + 2*k][pg], t[g8*8 + 2*k + 1][pg]);
            op[k] = *reinterpret_cast<unsigned*>(&h);
        }
        uint4* dst = (uint4*)(g_fht + (size_t)vb * PP * (NC/2));
        dst[(size_t)((y+1)*PW + (x+1)) * 8 + g8] = o4;
    }
}

// ---------------------------------------------------------------------------
// Tap-record precompute. grid (HW/256, NSC, NB), 256 threads.
// ---------------------------------------------------------------------------
__global__ void __launch_bounds__(256) k_setup(const float* __restrict__ scale_hypo,
                                              const float* __restrict__ depth_init) {
    const int pix = blockIdx.x * 256 + threadIdx.x;
    const int s   = blockIdx.y;
    const int b   = blockIdx.z;
    const float fx = (float)(pix & (NW-1));
    const float fy = (float)(pix >> 7);

    const float d = depth_init[b*HW + pix] * scale_hypo[b*NSC + s];
    const float CX = (float)NW / (float)(NW-1);
    const float CY = (float)NH / (float)(NH-1);

    uint4* recp = g_rec + ((size_t)(b*NSC + s)*HW + pix)*2;

    #pragma unroll
    for (int vv = 0; vv < 2; vv++) {
        const float* P = g_proj[vv*NB + b];
        float m0 = P[0]*fx + P[1]*fy + P[2];
        float m1 = P[3]*fx + P[4]*fy + P[5];
        float m2 = P[6]*fx + P[7]*fy + P[8];
        float px = fmaf(m0, d, P[9]);
        float py = fmaf(m1, d, P[10]);
        float pz = fmaf(m2, d, P[11]);
        float rz = __fdividef(1.0f, pz);
        float ix = fmaf(px*rz, CX, -0.5f);
        float iy = fmaf(py*rz, CY, -0.5f);
        // clamp into padded-safe range; reproduces zeros padding exactly
        ix = fminf(fmaxf(ix, -1.0f), (float)NW);
        iy = fminf(fmaxf(iy, -1.0f), (float)NH);
        float x0f = floorf(ix), y0f = floorf(iy);
        float wx1 = ix - x0f, wx0 = 1.0f - wx1;
        float wy1 = iy - y0f, wy0 = 1.0f - wy1;
        int x0p = (int)x0f + 1;          // 0..129
        int y0p = (int)y0f + 1;          // 0..129
        uint4 rec;
        rec.x = (unsigned)((y0p*PW + x0p) << 3);   // uint4 units (8 per pixel)
        rec.y = packh2(__float2half_rn(wx0*wy0), __float2half_rn(wx1*wy0));
        rec.z = packh2(__float2half_rn(wx0*wy1), __float2half_rn(wx1*wy1));
        rec.w = 0;
        recp[vv] = rec;
    }
}

// ---------------------------------------------------------------------------
// Main gather kernel (R6 verbatim). 256 threads = 32 pixels x 8 channel-lanes.
// No barriers inside the scale loop; records prefetched one scale ahead.
// ---------------------------------------------------------------------------
__global__ void __launch_bounds__(256) k_main() {
    const int b   = blockIdx.y;
    const int tid = threadIdx.x;
    const int w   = tid >> 5;
    const int l   = tid & 31;
    const int pg  = (w << 2) | (l >> 3);   // pixel in block 0..31
    const int cl  = l & 7;                 // channel chunk 0..7
    const int pix = blockIdx.x * PIX_PER_BLK + pg;

    __shared__ float s_part[NSC][8];

    const uint4* f0 = (const uint4*)(g_fht + (size_t)(0*NB + b)*PP*(NC/2)) + cl;
    const uint4* f1 = (const uint4*)(g_fht + (size_t)(1*NB + b)*PP*(NC/2)) + cl;
    const uint4* f2 = (const uint4*)(g_fht + (size_t)(2*NB + b)*PP*(NC/2)) + cl;

    __half2 r0h[4];
    {
        int pixp = ((pix >> 7) + 1)*PW + (pix & 127) + 1;
        uint4 q = f0[pixp << 3];
        r0h[0] = u2h2(q.x); r0h[1] = u2h2(q.y);
        r0h[2] = u2h2(q.z); r0h[3] = u2h2(q.w);
    }

    const uint4* rp = g_rec + ((size_t)(b*NSC + 0)*HW + pix)*2;
    uint4 ra = rp[0];
    uint4 rb = rp[1];

    #pragma unroll 1
    for (int s = 0; s < NSC; s++) {
        // prefetch next scale's records
        uint4 na, nb;
        if (s + 1 < NSC) {
            const uint4* np = rp + (size_t)2*HW;
            na = np[0];
            nb = np[1];
        }

        const __half2 zero = __float2half2_rn(0.0f);
        const int o1 = (int)ra.x;
        const int o2 = (int)rb.x;
        __half2 w1lo = u2h2(ra.y);   // (w00, w01)
        __half2 w1hi = u2h2(ra.z);   // (w02, w03)
        __half2 w2lo = u2h2(rb.y);
        __half2 w2hi = u2h2(rb.z);

        // view 1 (4 taps)
        __half2 s1[4] = {zero, zero, zero, zero};
        {
            uint4 q; __half2 ww;
            q = f1[o1];               ww = __low2half2(w1lo);
            s1[0]=__hfma2(u2h2(q.x),ww,s1[0]); s1[1]=__hfma2(u2h2(q.y),ww,s1[1]);
            s1[2]=__hfma2(u2h2(q.z),ww,s1[2]); s1[3]=__hfma2(u2h2(q.w),ww,s1[3]);
            q = f1[o1 + 8];           ww = __high2half2(w1lo);
            s1[0]=__hfma2(u2h2(q.x),ww,s1[0]); s1[1]=__hfma2(u2h2(q.y),ww,s1[1]);
            s1[2]=__hfma2(u2h2(q.z),ww,s1[2]); s1[3]=__hfma2(u2h2(q.w),ww,s1[3]);
            q = f1[o1 + (PW<<3)];     ww = __low2half2(w1hi);
            s1[0]=__hfma2(u2h2(q.x),ww,s1[0]); s1[1]=__hfma2(u2h2(q.y),ww,s1[1]);
            s1[2]=__hfma2(u2h2(q.z),ww,s1[2]); s1[3]=__hfma2(u2h2(q.w),ww,s1[3]);
            q = f1[o1 + (PW<<3) + 8]; ww = __high2half2(w1hi);
            s1[0]=__hfma2(u2h2(q.x),ww,s1[0]); s1[1]=__hfma2(u2h2(q.y),ww,s1[1]);
            s1[2]=__hfma2(u2h2(q.z),ww,s1[2]); s1[3]=__hfma2(u2h2(q.w),ww,s1[3]);
        }
        __half2 r1h[4];
        __half2 acc1h = zero;
        #pragma unroll
        for (int c = 0; c < 4; c++) {
            r1h[c] = __hsub2(r0h[c], s1[c]);
            acc1h = __hfma2(r1h[c], r1h[c], acc1h);
        }

        // view 2 (4 taps)
        __half2 s2[4] = {zero, zero, zero, zero};
        {
            uint4 q; __half2 ww;
            q = f2[o2];               ww = __low2half2(w2lo);
            s2[0]=__hfma2(u2h2(q.x),ww,s2[0]); s2[1]=__hfma2(u2h2(q.y),ww,s2[1]);
            s2[2]=__hfma2(u2h2(q.z),ww,s2[2]); s2[3]=__hfma2(u2h2(q.w),ww,s2[3]);
            q = f2[o2 + 8];           ww = __high2half2(w2lo);
            s2[0]=__hfma2(u2h2(q.x),ww,s2[0]); s2[1]=__hfma2(u2h2(q.y),ww,s2[1]);
            s2[2]=__hfma2(u2h2(q.z),ww,s2[2]); s2[3]=__hfma2(u2h2(q.w),ww,s2[3]);
            q = f2[o2 + (PW<<3)];     ww = __low2half2(w2hi);
            s2[0]=__hfma2(u2h2(q.x),ww,s2[0]); s2[1]=__hfma2(u2h2(q.y),ww,s2[1]);
            s2[2]=__hfma2(u2h2(q.z),ww,s2[2]); s2[3]=__hfma2(u2h2(q.w),ww,s2[3]);
            q = f2[o2 + (PW<<3) + 8]; ww = __high2half2(w2hi);
            s2[0]=__hfma2(u2h2(q.x),ww,s2[0]); s2[1]=__hfma2(u2h2(q.y),ww,s2[1]);
            s2[2]=__hfma2(u2h2(q.z),ww,s2[2]); s2[3]=__hfma2(u2h2(q.w),ww,s2[3]);
        }
        __half2 acc2h = zero;
        #pragma unroll
        for (int c = 0; c < 4; c++) {
            __half2 r2 = __hsub2(r1h[c], s2[c]);
            acc2h = __hfma2(r2, r2, acc2h);
        }

        float2 a1 = __half22float2(acc1h);
        float2 a2 = __half22float2(acc2h);
        float acc1 = a1.x + a1.y;
        float acc2 = a2.x + a2.y;

        #pragma unroll
        for (int o = 4; o > 0; o >>= 1) {
            acc1 += __shfl_xor_sync(0xffffffffu, acc1, o);
            acc2 += __shfl_xor_sync(0xffffffffu, acc2, o);
        }
        float cst = sqrtf(acc1) + sqrtf(acc2);
        cst += __shfl_xor_sync(0xffffffffu, cst, 8);
        cst += __shfl_xor_sync(0xffffffffu, cst, 16);
        if (l == 0) s_part[s][w] = cst;

        ra = na; rb = nb;
        rp += (size_t)2*HW;
    }

    __syncthreads();
    if (tid < NSC) {
        float v = 0.0f;
        #pragma unroll
        for (int i = 0; i < 8; i++) v += s_part[tid][i];
        g_partial[(b*NSC + tid)*GRIDX + blockIdx.x] = v;
    }
}

// ---------------------------------------------------------------------------
// Fused reduce + softmax. grid = NB, 1024 threads.
// ---------------------------------------------------------------------------
__global__ void __launch_bounds__(1024) k_redfin(const float* __restrict__ scale_hypo,
                                                float* __restrict__ out) {
    const int b    = blockIdx.x;
    const int wid  = threadIdx.x >> 5;
    const int lane = threadIdx.x & 31;

    const float4* p = (const float4*)(g_partial + (b*NSC + wid)*GRIDX);
    float v = 0.0f;
    #pragma unroll
    for (int i = 0; i < 4; i++) {
        float4 t = p[lane + 32*i];
        v += t.x + t.y + t.z + t.w;
    }
    #pragma unroll
    for (int o = 16; o > 0; o >>= 1)
        v += __shfl_xor_sync(0xffffffffu, v, o);

    __shared__ float sc[NSC];
    if (lane == 0) sc[wid] = v * (1.0f / (2.0f * (float)HW));
    __syncthreads();

    if (wid == 0) {
        float cost = sc[lane];
        float m = cost;
        #pragma unroll
        for (int o = 16; o > 0; o >>= 1)
            m = fmaxf(m, __shfl_xor_sync(0xffffffffu, m, o));
        float e = expf(cost - m);
        float shp = scale_hypo[b*NSC + lane];
        float den = e, num = e * shp;
        #pragma unroll
        for (int o = 16; o > 0; o >>= 1) {
            den += __shfl_xor_sync(0xffffffffu, den, o);
            num += __shfl_xor_sync(0xffffffffu, num, o);
        }
        if (lane == 0) out[b] = num / den;
    }
}

extern "C" void kernel_launch(void* const* d_in, const int* in_sizes, int n_in,
                              void* d_out, int out_size) {
    const float* feat  = (const float*)d_in[0];
    const float* intr  = (const float*)d_in[1];
    const float* c2w   = (const float*)d_in[2];
    const float* scale = (const float*)d_in[3];
    const float* depth = (const float*)d_in[4];
    float* out = (float*)d_out;

    dim3 trg(HW/32, NV*NB);
    k_tr<<<trg, 256>>>(feat, intr, c2w);
    dim3 sg(HW/256, NSC, NB);
    k_setup<<<sg, 256>>>(scale, depth);
    dim3 grid(GRIDX, NB);
    k_main<<<grid, 256>>>();
    k_redfin<<<NB, 1024>>>(scale, out);
}

// round 14
// speedup vs baseline: 1.3536x; 1.2372x over previous
#include <cuda_runtime.h>
#include <cuda_fp16.h>
#include <cuda_fp8.h>
#include <math.h>

#define NV 3
#define NB 2
#define NC 64
#define NSC 32
#define NH 128
#define NW 128
#define HW (NH*NW)
#define PW 131                      // padded width  (1 left, 2 right)
#define PH 131                      // padded height (1 top, 2 bottom)
#define PP (PW*PH)
#define PIX_PER_BLK 32
#define GRIDX (HW/PIX_PER_BLK)      // 512

// Allocation-free scratch (zero-initialized; padding rings stay 0).
__device__ float g_proj[(NV-1)*NB][12];
__device__ float g_partial[NB*NSC*GRIDX];
__device__ __align__(16) __half2 g_f0h[(size_t)NB*PP*(NC/2)];          // ref view fp16 padded
__device__ __align__(16) unsigned char g_f8[(size_t)(NV-1)*NB*PP*NC];  // views 1,2 fp8 padded
// Tap records: per (b,s,pix,view): {base_off(8-per-pixel units), pack(w0,w1), pack(w2,w3), 0}
__device__ __align__(16) uint4 g_rec[(size_t)NB*NSC*HW*2];

__device__ __forceinline__ void mat3mul(const float* A, const float* B, float* C) {
    #pragma unroll
    for (int i = 0; i < 3; i++)
        #pragma unroll
        for (int j = 0; j < 3; j++)
            C[i*3+j] = A[i*3+0]*B[0*3+j] + A[i*3+1]*B[1*3+j] + A[i*3+2]*B[2*3+j];
}
__device__ __forceinline__ void mat3vec(const float* A, const float* v, float* r) {
    #pragma unroll
    for (int i = 0; i < 3; i++)
        r[i] = A[i*3+0]*v[0] + A[i*3+1]*v[1] + A[i*3+2]*v[2];
}
__device__ __forceinline__ void mat3inv(const float* A, float* Ai) {
    float a=A[0],b=A[1],c=A[2],d=A[3],e=A[4],f=A[5],g=A[6],h=A[7],i=A[8];
    float det = a*(e*i-f*h) - b*(d*i-f*g) + c*(d*h-e*g);
    float inv = 1.0f / det;
    Ai[0] =  (e*i - f*h)*inv; Ai[1] = -(b*i - c*h)*inv; Ai[2] =  (b*f - c*e)*inv;
    Ai[3] = -(d*i - f*g)*inv; Ai[4] =  (a*i - c*g)*inv; Ai[5] = -(a*f - c*d)*inv;
    Ai[6] =  (d*h - e*g)*inv; Ai[7] = -(a*h - b*g)*inv; Ai[8] =  (a*e - b*d)*inv;
}
__device__ __forceinline__ __half2 u2h2(unsigned u) {
    return *reinterpret_cast<__half2*>(&u);
}
__device__ __forceinline__ unsigned packh2(__half a, __half b) {
    __half2 h = __halves2half2(a, b);
    return *reinterpret_cast<unsigned*>(&h);
}
__device__ __forceinline__ __half2 f8x2h2(unsigned short v) {
    __half2_raw r = __nv_cvt_fp8x2_to_halfraw2((__nv_fp8x2_storage_t)v, __NV_E4M3);
    return *reinterpret_cast<__half2*>(&r);
}

// ---------------------------------------------------------------------------
// Transpose (C,HW) -> padded (PH,PW,C); view0 fp16, views 1,2 fp8(e4m3).
// Homography prep fused into block (0,0). grid (HW/32, V*B), 256 threads.
// ---------------------------------------------------------------------------
__global__ void __launch_bounds__(256) k_tr(const float* __restrict__ feat,
                                            const float* __restrict__ intr,
                                            const float* __restrict__ c2w) {
    if (blockIdx.x == 0 && blockIdx.y == 0 && threadIdx.x < (NV-1)*NB) {
        int tid = threadIdx.x;
        int v = 1 + tid / NB;
        int b = tid % NB;
        const float* Kr = intr + (0*NB + b)*9;
        const float* Tr = c2w  + (0*NB + b)*16;
        const float* Ks = intr + (v*NB + b)*9;
        const float* Ts = c2w  + (v*NB + b)*16;

        float RrT[9], RsT[9], tr[3], ts[3];
        #pragma unroll
        for (int i = 0; i < 3; i++) {
            #pragma unroll
            for (int j = 0; j < 3; j++) {
                RrT[j*3+i] = Tr[i*4+j];
                RsT[j*3+i] = Ts[i*4+j];
            }
            tr[i] = Tr[i*4+3];
            ts[i] = Ts[i*4+3];
        }
        float trw[3], tsw[3], tmp[3];
        mat3vec(RrT, tr, tmp); trw[0]=-tmp[0]; trw[1]=-tmp[1]; trw[2]=-tmp[2];
        mat3vec(RsT, ts, tmp); tsw[0]=-tmp[0]; tsw[1]=-tmp[1]; tsw[2]=-tmp[2];

        float A[9], bref[3], Ai[9];
        mat3mul(Kr, RrT, A);
        mat3vec(Kr, trw, tmp);
        bref[0]=tmp[0]+trw[0]; bref[1]=tmp[1]+trw[1]; bref[2]=tmp[2]+trw[2];
        mat3inv(A, Ai);

        float SM[9], St[3];
        mat3mul(Ks, RsT, SM);
        mat3vec(Ks, tsw, tmp);
        St[0]=tmp[0]+tsw[0]; St[1]=tmp[1]+tsw[1]; St[2]=tmp[2]+tsw[2];

        float M[9], Mb[3];
        mat3mul(SM, Ai, M);
        mat3vec(M, bref, Mb);

        float* o = g_proj[(v-1)*NB + b];
        #pragma unroll
        for (int i = 0; i < 9; i++) o[i] = M[i];
        o[9]  = St[0] - Mb[0];
        o[10] = St[1] - Mb[1];
        o[11] = St[2] - Mb[2];
    }

    __shared__ float t[NC][33];
    const int vb  = blockIdx.y;
    const int v   = vb >> 1;         // NB == 2
    const int b   = vb & 1;
    const int hw0 = blockIdx.x * 32;
    const int tid = threadIdx.x;
    const float* src = feat + (size_t)vb * NC * HW;

    // vectorized read: 512 float4 loads (2 per thread)
    #pragma unroll
    for (int i = tid; i < NC*8; i += 256) {
        int c = i >> 3, j4 = (i & 7) << 2;
        float4 v4 = *(const float4*)(src + (size_t)c * HW + hw0 + j4);
        t[c][j4+0] = v4.x; t[c][j4+1] = v4.y; t[c][j4+2] = v4.z; t[c][j4+3] = v4.w;
    }
    __syncthreads();

    {
        int pg = tid >> 3;           // pixel 0..31
        int g8 = tid & 7;            // channel-group of 8
        int g  = hw0 + pg;
        int y  = g >> 7, x = g & 127;
        size_t ppix = (size_t)((y+1)*PW + (x+1));

        if (v == 0) {
            // ref view: fp16, one uint4 (8 channels) per thread
            uint4 o4;
            unsigned* op = &o4.x;
            #pragma unroll
            for (int k = 0; k < 4; k++) {
                __half2 h = __floats2half2_rn(t[g8*8 + 2*k][pg], t[g8*8 + 2*k + 1][pg]);
                op[k] = *reinterpret_cast<unsigned*>(&h);
            }
            uint4* dst = (uint4*)(g_f0h + (size_t)b * PP * (NC/2));
            dst[ppix * 8 + g8] = o4;
        } else {
            // warped views: fp8 e4m3, one uint2 (8 channels) per thread
            unsigned short s0 = __nv_cvt_float2_to_fp8x2(
                make_float2(t[g8*8+0][pg], t[g8*8+1][pg]), __NV_SATFINITE, __NV_E4M3);
            unsigned short s1 = __nv_cvt_float2_to_fp8x2(
                make_float2(t[g8*8+2][pg], t[g8*8+3][pg]), __NV_SATFINITE, __NV_E4M3);
            unsigned short s2 = __nv_cvt_float2_to_fp8x2(
                make_float2(t[g8*8+4][pg], t[g8*8+5][pg]), __NV_SATFINITE, __NV_E4M3);
            unsigned short s3 = __nv_cvt_float2_to_fp8x2(
                make_float2(t[g8*8+6][pg], t[g8*8+7][pg]), __NV_SATFINITE, __NV_E4M3);
            uint2 o2v;
            o2v.x = (unsigned)s0 | ((unsigned)s1 << 16);
            o2v.y = (unsigned)s2 | ((unsigned)s3 << 16);
            uint2* dst = (uint2*)(g_f8 + (size_t)((v-1)*NB + b) * PP * NC);
            dst[ppix * 8 + g8] = o2v;
        }
    }
}

// ---------------------------------------------------------------------------
// Tap-record precompute (R13 verbatim). grid (HW/256, NSC, NB), 256 threads.
// rec.x units are "8 per pixel" — valid for uint2 (fp8) indexing too.
// ---------------------------------------------------------------------------
__global__ void __launch_bounds__(256) k_setup(const float* __restrict__ scale_hypo,
                                              const float* __restrict__ depth_init) {
    const int pix = blockIdx.x * 256 + threadIdx.x;
    const int s   = blockIdx.y;
    const int b   = blockIdx.z;
    const float fx = (float)(pix & (NW-1));
    const float fy = (float)(pix >> 7);

    const float d = depth_init[b*HW + pix] * scale_hypo[b*NSC + s];
    const float CX = (float)NW / (float)(NW-1);
    const float CY = (float)NH / (float)(NH-1);

    uint4* recp = g_rec + ((size_t)(b*NSC + s)*HW + pix)*2;

    #pragma unroll
    for (int vv = 0; vv < 2; vv++) {
        const float* P = g_proj[vv*NB + b];
        float m0 = P[0]*fx + P[1]*fy + P[2];
        float m1 = P[3]*fx + P[4]*fy + P[5];
        float m2 = P[6]*fx + P[7]*fy + P[8];
        float px = fmaf(m0, d, P[9]);
        float py = fmaf(m1, d, P[10]);
        float pz = fmaf(m2, d, P[11]);
        float rz = __fdividef(1.0f, pz);
        float ix = fmaf(px*rz, CX, -0.5f);
        float iy = fmaf(py*rz, CY, -0.5f);
        // clamp into padded-safe range; reproduces zeros padding exactly
        ix = fminf(fmaxf(ix, -1.0f), (float)NW);
        iy = fminf(fmaxf(iy, -1.0f), (float)NH);
        float x0f = floorf(ix), y0f = floorf(iy);
        float wx1 = ix - x0f, wx0 = 1.0f - wx1;
        float wy1 = iy - y0f, wy0 = 1.0f - wy1;
        int x0p = (int)x0f + 1;          // 0..129
        int y0p = (int)y0f + 1;          // 0..129
        uint4 rec;
        rec.x = (unsigned)((y0p*PW + x0p) << 3);
        rec.y = packh2(__float2half_rn(wx0*wy0), __float2half_rn(wx1*wy0));
        rec.z = packh2(__float2half_rn(wx0*wy1), __float2half_rn(wx1*wy1));
        rec.w = 0;
        recp[vv] = rec;
    }
}

// ---------------------------------------------------------------------------
// Main gather kernel. 256 threads = 32 pixels x 8 channel-lanes.
// Warped taps load as fp8 uint2 (2 lines/warp-tap), cvt to half2, HFMA2.
// No barriers in scale loop; records prefetched one scale ahead (R6 pattern).
// ---------------------------------------------------------------------------
__global__ void __launch_bounds__(256) k_main() {
    const int b   = blockIdx.y;
    const int tid = threadIdx.x;
    const int w   = tid >> 5;
    const int l   = tid & 31;
    const int pg  = (w << 2) | (l >> 3);   // pixel in block 0..31
    const int cl  = l & 7;                 // channel chunk 0..7
    const int pix = blockIdx.x * PIX_PER_BLK + pg;

    __shared__ float s_part[NSC][8];

    const uint4* f0 = (const uint4*)(g_f0h + (size_t)b*PP*(NC/2)) + cl;
    const uint2* f1 = (const uint2*)(g_f8 + (size_t)(0*NB + b)*PP*NC) + cl;
    const uint2* f2 = (const uint2*)(g_f8 + (size_t)(1*NB + b)*PP*NC) + cl;

    __half2 r0h[4];
    {
        int pixp = ((pix >> 7) + 1)*PW + (pix & 127) + 1;
        uint4 q = f0[pixp << 3];
        r0h[0] = u2h2(q.x); r0h[1] = u2h2(q.y);
        r0h[2] = u2h2(q.z); r0h[3] = u2h2(q.w);
    }

    const uint4* rp = g_rec + ((size_t)(b*NSC + 0)*HW + pix)*2;
    uint4 ra = rp[0];
    uint4 rb = rp[1];

    #pragma unroll 1
    for (int s = 0; s < NSC; s++) {
        // prefetch next scale's records
        uint4 na, nb;
        if (s + 1 < NSC) {
            const uint4* np = rp + (size_t)2*HW;
            na = np[0];
            nb = np[1];
        }

        const __half2 zero = __float2half2_rn(0.0f);
        const int o1 = (int)ra.x;
        const int o2 = (int)rb.x;
        __half2 w1lo = u2h2(ra.y);   // (w00, w01)
        __half2 w1hi = u2h2(ra.z);   // (w02, w03)
        __half2 w2lo = u2h2(rb.y);
        __half2 w2hi = u2h2(rb.z);

        // view 1 (4 taps)
        __half2 s1[4] = {zero, zero, zero, zero};
        {
            uint2 q; __half2 ww;
            q = f1[o1];               ww = __low2half2(w1lo);
            s1[0]=__hfma2(f8x2h2((unsigned short)q.x),ww,s1[0]);
            s1[1]=__hfma2(f8x2h2((unsigned short)(q.x>>16)),ww,s1[1]);
            s1[2]=__hfma2(f8x2h2((unsigned short)q.y),ww,s1[2]);
            s1[3]=__hfma2(f8x2h2((unsigned short)(q.y>>16)),ww,s1[3]);
            q = f1[o1 + 8];           ww = __high2half2(w1lo);
            s1[0]=__hfma2(f8x2h2((unsigned short)q.x),ww,s1[0]);
            s1[1]=__hfma2(f8x2h2((unsigned short)(q.x>>16)),ww,s1[1]);
            s1[2]=__hfma2(f8x2h2((unsigned short)q.y),ww,s1[2]);
            s1[3]=__hfma2(f8x2h2((unsigned short)(q.y>>16)),ww,s1[3]);
            q = f1[o1 + (PW<<3)];     ww = __low2half2(w1hi);
            s1[0]=__hfma2(f8x2h2((unsigned short)q.x),ww,s1[0]);
            s1[1]=__hfma2(f8x2h2((unsigned short)(q.x>>16)),ww,s1[1]);
            s1[2]=__hfma2(f8x2h2((unsigned short)q.y),ww,s1[2]);
            s1[3]=__hfma2(f8x2h2((unsigned short)(q.y>>16)),ww,s1[3]);
            q = f1[o1 + (PW<<3) + 8]; ww = __high2half2(w1hi);
            s1[0]=__hfma2(f8x2h2((unsigned short)q.x),ww,s1[0]);
            s1[1]=__hfma2(f8x2h2((unsigned short)(q.x>>16)),ww,s1[1]);
            s1[2]=__hfma2(f8x2h2((unsigned short)q.y),ww,s1[2]);
            s1[3]=__hfma2(f8x2h2((unsigned short)(q.y>>16)),ww,s1[3]);
        }
        __half2 r1h[4];
        __half2 acc1h = zero;
        #pragma unroll
        for (int c = 0; c < 4; c++) {
            r1h[c] = __hsub2(r0h[c], s1[c]);
            acc1h = __hfma2(r1h[c], r1h[c], acc1h);
        }

        // view 2 (4 taps)
        __half2 s2[4] = {zero, zero, zero, zero};
        {
            uint2 q; __half2 ww;
            q = f2[o2];               ww = __low2half2(w2lo);
            s2[0]=__hfma2(f8x2h2((unsigned short)q.x),ww,s2[0]);
            s2[1]=__hfma2(f8x2h2((unsigned short)(q.x>>16)),ww,s2[1]);
            s2[2]=__hfma2(f8x2h2((unsigned short)q.y),ww,s2[2]);
            s2[3]=__hfma2(f8x2h2((unsigned short)(q.y>>16)),ww,s2[3]);
            q = f2[o2 + 8];           ww = __high2half2(w2lo);
            s2[0]=__hfma2(f8x2h2((unsigned short)q.x),ww,s2[0]);
            s2[1]=__hfma2(f8x2h2((unsigned short)(q.x>>16)),ww,s2[1]);
            s2[2]=__hfma2(f8x2h2((unsigned short)q.y),ww,s2[2]);
            s2[3]=__hfma2(f8x2h2((unsigned short)(q.y>>16)),ww,s2[3]);
            q = f2[o2 + (PW<<3)];     ww = __low2half2(w2hi);
            s2[0]=__hfma2(f8x2h2((unsigned short)q.x),ww,s2[0]);
            s2[1]=__hfma2(f8x2h2((unsigned short)(q.x>>16)),ww,s2[1]);
            s2[2]=__hfma2(f8x2h2((unsigned short)q.y),ww,s2[2]);
            s2[3]=__hfma2(f8x2h2((unsigned short)(q.y>>16)),ww,s2[3]);
            q = f2[o2 + (PW<<3) + 8]; ww = __high2half2(w2hi);
            s2[0]=__hfma2(f8x2h2((unsigned short)q.x),ww,s2[0]);
            s2[1]=__hfma2(f8x2h2((unsigned short)(q.x>>16)),ww,s2[1]);
            s2[2]=__hfma2(f8x2h2((unsigned short)q.y),ww,s2[2]);
            s2[3]=__hfma2(f8x2h2((unsigned short)(q.y>>16)),ww,s2[3]);
        }
        __half2 acc2h = zero;
        #pragma unroll
        for (int c = 0; c < 4; c++) {
            __half2 r2 = __hsub2(r1h[c], s2[c]);
            acc2h = __hfma2(r2, r2, acc2h);
        }

        float2 a1 = __half22float2(acc1h);
        float2 a2 = __half22float2(acc2h);
        float acc1 = a1.x + a1.y;
        float acc2 = a2.x + a2.y;

        #pragma unroll
        for (int o = 4; o > 0; o >>= 1) {
            acc1 += __shfl_xor_sync(0xffffffffu, acc1, o);
            acc2 += __shfl_xor_sync(0xffffffffu, acc2, o);
        }
        float cst = sqrtf(acc1) + sqrtf(acc2);
        cst += __shfl_xor_sync(0xffffffffu, cst, 8);
        cst += __shfl_xor_sync(0xffffffffu, cst, 16);
        if (l == 0) s_part[s][w] = cst;

        ra = na; rb = nb;
        rp += (size_t)2*HW;
    }

    __syncthreads();
    if (tid < NSC) {
        float v = 0.0f;
        #pragma unroll
        for (int i = 0; i < 8; i++) v += s_part[tid][i];
        g_partial[(b*NSC + tid)*GRIDX + blockIdx.x] = v;
    }
}

// ---------------------------------------------------------------------------
// Fused reduce + softmax (R13 verbatim). grid = NB, 1024 threads.
// ---------------------------------------------------------------------------
__global__ void __launch_bounds__(1024) k_redfin(const float* __restrict__ scale_hypo,
                                                float* __restrict__ out) {
    const int b    = blockIdx.x;
    const int wid  = threadIdx.x >> 5;
    const int lane = threadIdx.x & 31;

    const float4* p = (const float4*)(g_partial + (b*NSC + wid)*GRIDX);
    float v = 0.0f;
    #pragma unroll
    for (int i = 0; i < 4; i++) {
        float4 t = p[lane + 32*i];
        v += t.x + t.y + t.z + t.w;
    }
    #pragma unroll
    for (int o = 16; o > 0; o >>= 1)
        v += __shfl_xor_sync(0xffffffffu, v, o);

    __shared__ float sc[NSC];
    if (lane == 0) sc[wid] = v * (1.0f / (2.0f * (float)HW));
    __syncthreads();

    if (wid == 0) {
        float cost = sc[lane];
        float m = cost;
        #pragma unroll
        for (int o = 16; o > 0; o >>= 1)
            m = fmaxf(m, __shfl_xor_sync(0xffffffffu, m, o));
        float e = expf(cost - m);
        float shp = scale_hypo[b*NSC + lane];
        float den = e, num = e * shp;
        #pragma unroll
        for (int o = 16; o > 0; o >>= 1) {
            den += __shfl_xor_sync(0xffffffffu, den, o);
            num += __shfl_xor_sync(0xffffffffu, num, o);
        }
        if (lane == 0) out[b] = num / den;
    }
}

extern "C" void kernel_launch(void* const* d_in, const int* in_sizes, int n_in,
                              void* d_out, int out_size) {
    const float* feat  = (const float*)d_in[0];
    const float* intr  = (const float*)d_in[1];
    const float* c2w   = (const float*)d_in[2];
    const float* scale = (const float*)d_in[3];
    const float* depth = (const float*)d_in[4];
    float* out = (float*)d_out;

    dim3 trg(HW/32, NV*NB);
    k_tr<<<trg, 256>>>(feat, intr, c2w);
    dim3 sg(HW/256, NSC, NB);
    k_setup<<<sg, 256>>>(scale, depth);
    dim3 grid(GRIDX, NB);
    k_main<<<grid, 256>>>();
    k_redfin<<<NB, 1024>>>(scale, out);
}

// round 15
// speedup vs baseline: 1.3943x; 1.0301x over previous
#include <cuda_runtime.h>
#include <cuda_fp16.h>
#include <cuda_fp8.h>
#include <math.h>

#define NV 3
#define NB 2
#define NC 64
#define NSC 32
#define NH 128
#define NW 128
#define HW (NH*NW)
#define PW 131                      // padded width  (1 left, 2 right)
#define PH 131                      // padded height (1 top, 2 bottom)
#define PP (PW*PH)
#define PIX_PER_BLK 64              // 256 threads = 64 pixels x 4 lanes
#define GRIDX (HW/PIX_PER_BLK)      // 256

// Allocation-free scratch (zero-initialized; padding rings stay 0).
__device__ float g_proj[(NV-1)*NB][12];
__device__ float g_partial[NB*NSC*GRIDX];
__device__ __align__(16) __half2 g_f0h[(size_t)NB*PP*(NC/2)];          // ref view fp16 padded
__device__ __align__(16) unsigned char g_f8[(size_t)(NV-1)*NB*PP*NC];  // views 1,2 fp8 padded
// Tap records: per (b,s,pix,view): {base_off(8-per-pixel units), pack(w0,w1), pack(w2,w3), 0}
__device__ __align__(16) uint4 g_rec[(size_t)NB*NSC*HW*2];

__device__ __forceinline__ void mat3mul(const float* A, const float* B, float* C) {
    #pragma unroll
    for (int i = 0; i < 3; i++)
        #pragma unroll
        for (int j = 0; j < 3; j++)
            C[i*3+j] = A[i*3+0]*B[0*3+j] + A[i*3+1]*B[1*3+j] + A[i*3+2]*B[2*3+j];
}
__device__ __forceinline__ void mat3vec(const float* A, const float* v, float* r) {
    #pragma unroll
    for (int i = 0; i < 3; i++)
        r[i] = A[i*3+0]*v[0] + A[i*3+1]*v[1] + A[i*3+2]*v[2];
}
__device__ __forceinline__ void mat3inv(const float* A, float* Ai) {
    float a=A[0],b=A[1],c=A[2],d=A[3],e=A[4],f=A[5],g=A[6],h=A[7],i=A[8];
    float det = a*(e*i-f*h) - b*(d*i-f*g) + c*(d*h-e*g);
    float inv = 1.0f / det;
    Ai[0] =  (e*i - f*h)*inv; Ai[1] = -(b*i - c*h)*inv; Ai[2] =  (b*f - c*e)*inv;
    Ai[3] = -(d*i - f*g)*inv; Ai[4] =  (a*i - c*g)*inv; Ai[5] = -(a*f - c*d)*inv;
    Ai[6] =  (d*h - e*g)*inv; Ai[7] = -(a*h - b*g)*inv; Ai[8] =  (a*e - b*d)*inv;
}
__device__ __forceinline__ __half2 u2h2(unsigned u) {
    return *reinterpret_cast<__half2*>(&u);
}
__device__ __forceinline__ unsigned packh2(__half a, __half b) {
    __half2 h = __halves2half2(a, b);
    return *reinterpret_cast<unsigned*>(&h);
}
__device__ __forceinline__ __half2 f8x2h2(unsigned short v) {
    __half2_raw r = __nv_cvt_fp8x2_to_halfraw2((__nv_fp8x2_storage_t)v, __NV_E4M3);
    return *reinterpret_cast<__half2*>(&r);
}

// Accumulate one fp8 tap (16 channels in uint4) into 8 half2 accumulators.
#define ACC_TAP(Fp, idx, ww, S) do {                                  \
    uint4 q = (Fp)[idx];                                              \
    S[0]=__hfma2(f8x2h2((unsigned short)q.x),        (ww), S[0]);     \
    S[1]=__hfma2(f8x2h2((unsigned short)(q.x>>16)),  (ww), S[1]);     \
    S[2]=__hfma2(f8x2h2((unsigned short)q.y),        (ww), S[2]);     \
    S[3]=__hfma2(f8x2h2((unsigned short)(q.y>>16)),  (ww), S[3]);     \
    S[4]=__hfma2(f8x2h2((unsigned short)q.z),        (ww), S[4]);     \
    S[5]=__hfma2(f8x2h2((unsigned short)(q.z>>16)),  (ww), S[5]);     \
    S[6]=__hfma2(f8x2h2((unsigned short)q.w),        (ww), S[6]);     \
    S[7]=__hfma2(f8x2h2((unsigned short)(q.w>>16)),  (ww), S[7]);     \
} while (0)

// ---------------------------------------------------------------------------
// Transpose (C,HW) -> padded (PH,PW,C); view0 fp16, views 1,2 fp8(e4m3).
// Homography prep fused into block (0,0). grid (HW/32, V*B), 256 threads.
// (R14 verbatim — passing.)
// ---------------------------------------------------------------------------
__global__ void __launch_bounds__(256) k_tr(const float* __restrict__ feat,
                                            const float* __restrict__ intr,
                                            const float* __restrict__ c2w) {
    if (blockIdx.x == 0 && blockIdx.y == 0 && threadIdx.x < (NV-1)*NB) {
        int tid = threadIdx.x;
        int v = 1 + tid / NB;
        int b = tid % NB;
        const float* Kr = intr + (0*NB + b)*9;
        const float* Tr = c2w  + (0*NB + b)*16;
        const float* Ks = intr + (v*NB + b)*9;
        const float* Ts = c2w  + (v*NB + b)*16;

        float RrT[9], RsT[9], tr[3], ts[3];
        #pragma unroll
        for (int i = 0; i < 3; i++) {
            #pragma unroll
            for (int j = 0; j < 3; j++) {
                RrT[j*3+i] = Tr[i*4+j];
                RsT[j*3+i] = Ts[i*4+j];
            }
            tr[i] = Tr[i*4+3];
            ts[i] = Ts[i*4+3];
        }
        float trw[3], tsw[3], tmp[3];
        mat3vec(RrT, tr, tmp); trw[0]=-tmp[0]; trw[1]=-tmp[1]; trw[2]=-tmp[2];
        mat3vec(RsT, ts, tmp); tsw[0]=-tmp[0]; tsw[1]=-tmp[1]; tsw[2]=-tmp[2];

        float A[9], bref[3], Ai[9];
        mat3mul(Kr, RrT, A);
        mat3vec(Kr, trw, tmp);
        bref[0]=tmp[0]+trw[0]; bref[1]=tmp[1]+trw[1]; bref[2]=tmp[2]+trw[2];
        mat3inv(A, Ai);

        float SM[9], St[3];
        mat3mul(Ks, RsT, SM);
        mat3vec(Ks, tsw, tmp);
        St[0]=tmp[0]+tsw[0]; St[1]=tmp[1]+tsw[1]; St[2]=tmp[2]+tsw[2];

        float M[9], Mb[3];
        mat3mul(SM, Ai, M);
        mat3vec(M, bref, Mb);

        float* o = g_proj[(v-1)*NB + b];
        #pragma unroll
        for (int i = 0; i < 9; i++) o[i] = M[i];
        o[9]  = St[0] - Mb[0];
        o[10] = St[1] - Mb[1];
        o[11] = St[2] - Mb[2];
    }

    __shared__ float t[NC][33];
    const int vb  = blockIdx.y;
    const int v   = vb >> 1;         // NB == 2
    const int b   = vb & 1;
    const int hw0 = blockIdx.x * 32;
    const int tid = threadIdx.x;
    const float* src = feat + (size_t)vb * NC * HW;

    #pragma unroll
    for (int i = tid; i < NC*8; i += 256) {
        int c = i >> 3, j4 = (i & 7) << 2;
        float4 v4 = *(const float4*)(src + (size_t)c * HW + hw0 + j4);
        t[c][j4+0] = v4.x; t[c][j4+1] = v4.y; t[c][j4+2] = v4.z; t[c][j4+3] = v4.w;
    }
    __syncthreads();

    {
        int pg = tid >> 3;           // pixel 0..31
        int g8 = tid & 7;            // channel-group of 8
        int g  = hw0 + pg;
        int y  = g >> 7, x = g & 127;
        size_t ppix = (size_t)((y+1)*PW + (x+1));

        if (v == 0) {
            uint4 o4;
            unsigned* op = &o4.x;
            #pragma unroll
            for (int k = 0; k < 4; k++) {
                __half2 h = __floats2half2_rn(t[g8*8 + 2*k][pg], t[g8*8 + 2*k + 1][pg]);
                op[k] = *reinterpret_cast<unsigned*>(&h);
            }
            uint4* dst = (uint4*)(g_f0h + (size_t)b * PP * (NC/2));
            dst[ppix * 8 + g8] = o4;
        } else {
            unsigned short s0 = __nv_cvt_float2_to_fp8x2(
                make_float2(t[g8*8+0][pg], t[g8*8+1][pg]), __NV_SATFINITE, __NV_E4M3);
            unsigned short s1 = __nv_cvt_float2_to_fp8x2(
                make_float2(t[g8*8+2][pg], t[g8*8+3][pg]), __NV_SATFINITE, __NV_E4M3);
            unsigned short s2 = __nv_cvt_float2_to_fp8x2(
                make_float2(t[g8*8+4][pg], t[g8*8+5][pg]), __NV_SATFINITE, __NV_E4M3);
            unsigned short s3 = __nv_cvt_float2_to_fp8x2(
                make_float2(t[g8*8+6][pg], t[g8*8+7][pg]), __NV_SATFINITE, __NV_E4M3);
            uint2 o2v;
            o2v.x = (unsigned)s0 | ((unsigned)s1 << 16);
            o2v.y = (unsigned)s2 | ((unsigned)s3 << 16);
            uint2* dst = (uint2*)(g_f8 + (size_t)((v-1)*NB + b) * PP * NC);
            dst[ppix * 8 + g8] = o2v;
        }
    }
}

// ---------------------------------------------------------------------------
// Tap-record precompute (R13/R14 verbatim). grid (HW/256, NSC, NB).
// ---------------------------------------------------------------------------
__global__ void __launch_bounds__(256) k_setup(const float* __restrict__ scale_hypo,
                                              const float* __restrict__ depth_init) {
    const int pix = blockIdx.x * 256 + threadIdx.x;
    const int s   = blockIdx.y;
    const int b   = blockIdx.z;
    const float fx = (float)(pix & (NW-1));
    const float fy = (float)(pix >> 7);

    const float d = depth_init[b*HW + pix] * scale_hypo[b*NSC + s];
    const float CX = (float)NW / (float)(NW-1);
    const float CY = (float)NH / (float)(NH-1);

    uint4* recp = g_rec + ((size_t)(b*NSC + s)*HW + pix)*2;

    #pragma unroll
    for (int vv = 0; vv < 2; vv++) {
        const float* P = g_proj[vv*NB + b];
        float m0 = P[0]*fx + P[1]*fy + P[2];
        float m1 = P[3]*fx + P[4]*fy + P[5];
        float m2 = P[6]*fx + P[7]*fy + P[8];
        float px = fmaf(m0, d, P[9]);
        float py = fmaf(m1, d, P[10]);
        float pz = fmaf(m2, d, P[11]);
        float rz = __fdividef(1.0f, pz);
        float ix = fmaf(px*rz, CX, -0.5f);
        float iy = fmaf(py*rz, CY, -0.5f);
        ix = fminf(fmaxf(ix, -1.0f), (float)NW);
        iy = fminf(fmaxf(iy, -1.0f), (float)NH);
        float x0f = floorf(ix), y0f = floorf(iy);
        float wx1 = ix - x0f, wx0 = 1.0f - wx1;
        float wy1 = iy - y0f, wy0 = 1.0f - wy1;
        int x0p = (int)x0f + 1;
        int y0p = (int)y0f + 1;
        uint4 rec;
        rec.x = (unsigned)((y0p*PW + x0p) << 3);
        rec.y = packh2(__float2half_rn(wx0*wy0), __float2half_rn(wx1*wy0));
        rec.z = packh2(__float2half_rn(wx0*wy1), __float2half_rn(wx1*wy1));
        rec.w = 0;
        recp[vv] = rec;
    }
}

// ---------------------------------------------------------------------------
// Main gather kernel. 256 threads = 64 pixels x 4 lanes (16 channels each).
// Halves warp count (4096 tasks = 27.7 warps/SM -> single wave) and halves
// tap LDG instruction count (one LDG.128 covers a full 16-channel chunk).
// ---------------------------------------------------------------------------
__global__ void __launch_bounds__(256) k_main() {
    const int b   = blockIdx.y;
    const int tid = threadIdx.x;
    const int w   = tid >> 5;               // warp 0..7
    const int l   = tid & 31;
    const int pgw = l >> 2;                 // pixel in warp 0..7
    const int cl  = l & 3;                  // channel chunk of 16
    const int pix = blockIdx.x * PIX_PER_BLK + (w << 3) + pgw;

    __shared__ float s_part[NSC][8];

    const uint4* f0 = (const uint4*)(g_f0h + (size_t)b*PP*(NC/2));
    const uint4* f1 = (const uint4*)(g_f8 + (size_t)(0*NB + b)*PP*NC) + cl;
    const uint4* f2 = (const uint4*)(g_f8 + (size_t)(1*NB + b)*PP*NC) + cl;

    // ref channels 16*cl .. 16*cl+15 (fp16, two uint4)
    __half2 r0h[8];
    {
        int pixp = ((pix >> 7) + 1)*PW + (pix & 127) + 1;
        uint4 qa = f0[(size_t)pixp*8 + cl*2];
        uint4 qb = f0[(size_t)pixp*8 + cl*2 + 1];
        r0h[0] = u2h2(qa.x); r0h[1] = u2h2(qa.y);
        r0h[2] = u2h2(qa.z); r0h[3] = u2h2(qa.w);
        r0h[4] = u2h2(qb.x); r0h[5] = u2h2(qb.y);
        r0h[6] = u2h2(qb.z); r0h[7] = u2h2(qb.w);
    }

    const uint4* rp = g_rec + ((size_t)(b*NSC + 0)*HW + pix)*2;
    uint4 ra = rp[0];
    uint4 rb = rp[1];

    #pragma unroll 1
    for (int s = 0; s < NSC; s++) {
        // prefetch next scale's records
        uint4 na, nb;
        if (s + 1 < NSC) {
            const uint4* np = rp + (size_t)2*HW;
            na = np[0];
            nb = np[1];
        }

        const __half2 zero = __float2half2_rn(0.0f);
        const int o1 = (int)(ra.x >> 1);   // uint4 units (4 per pixel)
        const int o2 = (int)(rb.x >> 1);
        __half2 w1lo = u2h2(ra.y);   // (w00, w01)
        __half2 w1hi = u2h2(ra.z);   // (w02, w03)
        __half2 w2lo = u2h2(rb.y);
        __half2 w2hi = u2h2(rb.z);

        // view 1 (4 taps x 16 channels)
        __half2 s1[8] = {zero, zero, zero, zero, zero, zero, zero, zero};
        ACC_TAP(f1, o1,               __low2half2(w1lo),  s1);
        ACC_TAP(f1, o1 + 4,           __high2half2(w1lo), s1);
        ACC_TAP(f1, o1 + (PW<<2),     __low2half2(w1hi),  s1);
        ACC_TAP(f1, o1 + (PW<<2) + 4, __high2half2(w1hi), s1);

        __half2 r1h[8];
        __half2 acc1h = zero;
        #pragma unroll
        for (int c = 0; c < 8; c++) {
            r1h[c] = __hsub2(r0h[c], s1[c]);
            acc1h = __hfma2(r1h[c], r1h[c], acc1h);
        }

        // view 2 (4 taps x 16 channels)
        __half2 s2[8] = {zero, zero, zero, zero, zero, zero, zero, zero};
        ACC_TAP(f2, o2,               __low2half2(w2lo),  s2);
        ACC_TAP(f2, o2 + 4,           __high2half2(w2lo), s2);
        ACC_TAP(f2, o2 + (PW<<2),     __low2half2(w2hi),  s2);
        ACC_TAP(f2, o2 + (PW<<2) + 4, __high2half2(w2hi), s2);

        __half2 acc2h = zero;
        #pragma unroll
        for (int c = 0; c < 8; c++) {
            __half2 r2 = __hsub2(r1h[c], s2[c]);
            acc2h = __hfma2(r2, r2, acc2h);
        }

        float2 a1 = __half22float2(acc1h);
        float2 a2 = __half22float2(acc2h);
        float acc1 = a1.x + a1.y;
        float acc2 = a2.x + a2.y;

        // reduce across 4 channel lanes
        #pragma unroll
        for (int o = 2; o > 0; o >>= 1) {
            acc1 += __shfl_xor_sync(0xffffffffu, acc1, o);
            acc2 += __shfl_xor_sync(0xffffffffu, acc2, o);
        }
        float cst = sqrtf(acc1) + sqrtf(acc2);
        // sum the warp's 8 pixels
        cst += __shfl_xor_sync(0xffffffffu, cst, 4);
        cst += __shfl_xor_sync(0xffffffffu, cst, 8);
        cst += __shfl_xor_sync(0xffffffffu, cst, 16);
        if (l == 0) s_part[s][w] = cst;

        ra = na; rb = nb;
        rp += (size_t)2*HW;
    }

    __syncthreads();
    if (tid < NSC) {
        float v = 0.0f;
        #pragma unroll
        for (int i = 0; i < 8; i++) v += s_part[tid][i];
        g_partial[(b*NSC + tid)*GRIDX + blockIdx.x] = v;
    }
}

// ---------------------------------------------------------------------------
// Fused reduce + softmax. grid = NB, 1024 threads; 256 partials per scale.
// ---------------------------------------------------------------------------
__global__ void __launch_bounds__(1024) k_redfin(const float* __restrict__ scale_hypo,
                                                float* __restrict__ out) {
    const int b    = blockIdx.x;
    const int wid  = threadIdx.x >> 5;
    const int lane = threadIdx.x & 31;

    const float4* p = (const float4*)(g_partial + (b*NSC + wid)*GRIDX);
    float v = 0.0f;
    #pragma unroll
    for (int i = 0; i < 2; i++) {
        float4 t = p[lane + 32*i];
        v += t.x + t.y + t.z + t.w;
    }
    #pragma unroll
    for (int o = 16; o > 0; o >>= 1)
        v += __shfl_xor_sync(0xffffffffu, v, o);

    __shared__ float sc[NSC];
    if (lane == 0) sc[wid] = v * (1.0f / (2.0f * (float)HW));
    __syncthreads();

    if (wid == 0) {
        float cost = sc[lane];
        float m = cost;
        #pragma unroll
        for (int o = 16; o > 0; o >>= 1)
            m = fmaxf(m, __shfl_xor_sync(0xffffffffu, m, o));
        float e = expf(cost - m);
        float shp = scale_hypo[b*NSC + lane];
        float den = e, num = e * shp;
        #pragma unroll
        for (int o = 16; o > 0; o >>= 1) {
            den += __shfl_xor_sync(0xffffffffu, den, o);
            num += __shfl_xor_sync(0xffffffffu, num, o);
        }
        if (lane == 0) out[b] = num / den;
    }
}

extern "C" void kernel_launch(void* const* d_in, const int* in_sizes, int n_in,
                              void* d_out, int out_size) {
    const float* feat  = (const float*)d_in[0];
    const float* intr  = (const float*)d_in[1];
    const float* c2w   = (const float*)d_in[2];
    const float* scale = (const float*)d_in[3];
    const float* depth = (const float*)d_in[4];
    float* out = (float*)d_out;

    dim3 trg(HW/32, NV*NB);
    k_tr<<<trg, 256>>>(feat, intr, c2w);
    dim3 sg(HW/256, NSC, NB);
    k_setup<<<sg, 256>>>(scale, depth);
    dim3 grid(GRIDX, NB);
    k_main<<<grid, 256>>>();
    k_redfin<<<NB, 1024>>>(scale, out);
}

// round 16
// speedup vs baseline: 1.4857x; 1.0656x over previous
#include <cuda_runtime.h>
#include <cuda_fp16.h>
#include <cuda_fp8.h>
#include <math.h>

#define NV 3
#define NB 2
#define NC 64
#define NSC 32
#define NH 128
#define NW 128
#define HW (NH*NW)
#define PW 131                      // padded width  (1 left, 2 right)
#define PH 131                      // padded height (1 top, 2 bottom)
#define PP (PW*PH)
#define PIX_PER_BLK 32              // 128 threads = 32 pixels x 4 lanes
#define GRIDX (HW/PIX_PER_BLK)      // 512

// Allocation-free scratch (zero-initialized; padding rings stay 0).
__device__ float g_proj[(NV-1)*NB][12];
__device__ float g_partial[NB*NSC*GRIDX];
__device__ __align__(16) __half2 g_f0h[(size_t)NB*PP*(NC/2)];          // ref view fp16 padded
__device__ __align__(16) unsigned char g_f8[(size_t)(NV-1)*NB*PP*NC];  // views 1,2 fp8 padded
// Tap records: per (b,s,pix,view): {base_off(8-per-pixel units), pack(w0,w1), pack(w2,w3), 0}
__device__ __align__(16) uint4 g_rec[(size_t)NB*NSC*HW*2];

__device__ __forceinline__ void mat3mul(const float* A, const float* B, float* C) {
    #pragma unroll
    for (int i = 0; i < 3; i++)
        #pragma unroll
        for (int j = 0; j < 3; j++)
            C[i*3+j] = A[i*3+0]*B[0*3+j] + A[i*3+1]*B[1*3+j] + A[i*3+2]*B[2*3+j];
}
__device__ __forceinline__ void mat3vec(const float* A, const float* v, float* r) {
    #pragma unroll
    for (int i = 0; i < 3; i++)
        r[i] = A[i*3+0]*v[0] + A[i*3+1]*v[1] + A[i*3+2]*v[2];
}
__device__ __forceinline__ void mat3inv(const float* A, float* Ai) {
    float a=A[0],b=A[1],c=A[2],d=A[3],e=A[4],f=A[5],g=A[6],h=A[7],i=A[8];
    float det = a*(e*i-f*h) - b*(d*i-f*g) + c*(d*h-e*g);
    float inv = 1.0f / det;
    Ai[0] =  (e*i - f*h)*inv; Ai[1] = -(b*i - c*h)*inv; Ai[2] =  (b*f - c*e)*inv;
    Ai[3] = -(d*i - f*g)*inv; Ai[4] =  (a*i - c*g)*inv; Ai[5] = -(a*f - c*d)*inv;
    Ai[6] =  (d*h - e*g)*inv; Ai[7] = -(a*h - b*g)*inv; Ai[8] =  (a*e - b*d)*inv;
}
__device__ __forceinline__ __half2 u2h2(unsigned u) {
    return *reinterpret_cast<__half2*>(&u);
}
__device__ __forceinline__ unsigned packh2(__half a, __half b) {
    __half2 h = __halves2half2(a, b);
    return *reinterpret_cast<unsigned*>(&h);
}
__device__ __forceinline__ __half2 f8x2h2(unsigned short v) {
    __half2_raw r = __nv_cvt_fp8x2_to_halfraw2((__nv_fp8x2_storage_t)v, __NV_E4M3);
    return *reinterpret_cast<__half2*>(&r);
}

// Accumulate one fp8 tap (16 channels in uint4) into 8 half2 accumulators.
#define ACC_TAP(Fp, idx, ww, S) do {                                  \
    uint4 q = (Fp)[idx];                                              \
    S[0]=__hfma2(f8x2h2((unsigned short)q.x),        (ww), S[0]);     \
    S[1]=__hfma2(f8x2h2((unsigned short)(q.x>>16)),  (ww), S[1]);     \
    S[2]=__hfma2(f8x2h2((unsigned short)q.y),        (ww), S[2]);     \
    S[3]=__hfma2(f8x2h2((unsigned short)(q.y>>16)),  (ww), S[3]);     \
    S[4]=__hfma2(f8x2h2((unsigned short)q.z),        (ww), S[4]);     \
    S[5]=__hfma2(f8x2h2((unsigned short)(q.z>>16)),  (ww), S[5]);     \
    S[6]=__hfma2(f8x2h2((unsigned short)q.w),        (ww), S[6]);     \
    S[7]=__hfma2(f8x2h2((unsigned short)(q.w>>16)),  (ww), S[7]);     \
} while (0)

// ---------------------------------------------------------------------------
// Transpose (C,HW) -> padded (PH,PW,C); view0 fp16, views 1,2 fp8(e4m3).
// Homography prep fused into block (0,0). grid (HW/32, V*B), 256 threads.
// (R14/R15 verbatim — passing.)
// ---------------------------------------------------------------------------
__global__ void __launch_bounds__(256) k_tr(const float* __restrict__ feat,
                                            const float* __restrict__ intr,
                                            const float* __restrict__ c2w) {
    if (blockIdx.x == 0 && blockIdx.y == 0 && threadIdx.x < (NV-1)*NB) {
        int tid = threadIdx.x;
        int v = 1 + tid / NB;
        int b = tid % NB;
        const float* Kr = intr + (0*NB + b)*9;
        const float* Tr = c2w  + (0*NB + b)*16;
        const float* Ks = intr + (v*NB + b)*9;
        const float* Ts = c2w  + (v*NB + b)*16;

        float RrT[9], RsT[9], tr[3], ts[3];
        #pragma unroll
        for (int i = 0; i < 3; i++) {
            #pragma unroll
            for (int j = 0; j < 3; j++) {
                RrT[j*3+i] = Tr[i*4+j];
                RsT[j*3+i] = Ts[i*4+j];
            }
            tr[i] = Tr[i*4+3];
            ts[i] = Ts[i*4+3];
        }
        float trw[3], tsw[3], tmp[3];
        mat3vec(RrT, tr, tmp); trw[0]=-tmp[0]; trw[1]=-tmp[1]; trw[2]=-tmp[2];
        mat3vec(RsT, ts, tmp); tsw[0]=-tmp[0]; tsw[1]=-tmp[1]; tsw[2]=-tmp[2];

        float A[9], bref[3], Ai[9];
        mat3mul(Kr, RrT, A);
        mat3vec(Kr, trw, tmp);
        bref[0]=tmp[0]+trw[0]; bref[1]=tmp[1]+trw[1]; bref[2]=tmp[2]+trw[2];
        mat3inv(A, Ai);

        float SM[9], St[3];
        mat3mul(Ks, RsT, SM);
        mat3vec(Ks, tsw, tmp);
        St[0]=tmp[0]+tsw[0]; St[1]=tmp[1]+tsw[1]; St[2]=tmp[2]+tsw[2];

        float M[9], Mb[3];
        mat3mul(SM, Ai, M);
        mat3vec(M, bref, Mb);

        float* o = g_proj[(v-1)*NB + b];
        #pragma unroll
        for (int i = 0; i < 9; i++) o[i] = M[i];
        o[9]  = St[0] - Mb[0];
        o[10] = St[1] - Mb[1];
        o[11] = St[2] - Mb[2];
    }

    __shared__ float t[NC][33];
    const int vb  = blockIdx.y;
    const int v   = vb >> 1;         // NB == 2
    const int b   = vb & 1;
    const int hw0 = blockIdx.x * 32;
    const int tid = threadIdx.x;
    const float* src = feat + (size_t)vb * NC * HW;

    #pragma unroll
    for (int i = tid; i < NC*8; i += 256) {
        int c = i >> 3, j4 = (i & 7) << 2;
        float4 v4 = *(const float4*)(src + (size_t)c * HW + hw0 + j4);
        t[c][j4+0] = v4.x; t[c][j4+1] = v4.y; t[c][j4+2] = v4.z; t[c][j4+3] = v4.w;
    }
    __syncthreads();

    {
        int pg = tid >> 3;           // pixel 0..31
        int g8 = tid & 7;            // channel-group of 8
        int g  = hw0 + pg;
        int y  = g >> 7, x = g & 127;
        size_t ppix = (size_t)((y+1)*PW + (x+1));

        if (v == 0) {
            uint4 o4;
            unsigned* op = &o4.x;
            #pragma unroll
            for (int k = 0; k < 4; k++) {
                __half2 h = __floats2half2_rn(t[g8*8 + 2*k][pg], t[g8*8 + 2*k + 1][pg]);
                op[k] = *reinterpret_cast<unsigned*>(&h);
            }
            uint4* dst = (uint4*)(g_f0h + (size_t)b * PP * (NC/2));
            dst[ppix * 8 + g8] = o4;
        } else {
            unsigned short s0 = __nv_cvt_float2_to_fp8x2(
                make_float2(t[g8*8+0][pg], t[g8*8+1][pg]), __NV_SATFINITE, __NV_E4M3);
            unsigned short s1 = __nv_cvt_float2_to_fp8x2(
                make_float2(t[g8*8+2][pg], t[g8*8+3][pg]), __NV_SATFINITE, __NV_E4M3);
            unsigned short s2 = __nv_cvt_float2_to_fp8x2(
                make_float2(t[g8*8+4][pg], t[g8*8+5][pg]), __NV_SATFINITE, __NV_E4M3);
            unsigned short s3 = __nv_cvt_float2_to_fp8x2(
                make_float2(t[g8*8+6][pg], t[g8*8+7][pg]), __NV_SATFINITE, __NV_E4M3);
            uint2 o2v;
            o2v.x = (unsigned)s0 | ((unsigned)s1 << 16);
            o2v.y = (unsigned)s2 | ((unsigned)s3 << 16);
            uint2* dst = (uint2*)(g_f8 + (size_t)((v-1)*NB + b) * PP * NC);
            dst[ppix * 8 + g8] = o2v;
        }
    }
}

// ---------------------------------------------------------------------------
// Tap-record precompute (verbatim). grid (HW/256, NSC, NB).
// ---------------------------------------------------------------------------
__global__ void __launch_bounds__(256) k_setup(const float* __restrict__ scale_hypo,
                                              const float* __restrict__ depth_init) {
    const int pix = blockIdx.x * 256 + threadIdx.x;
    const int s   = blockIdx.y;
    const int b   = blockIdx.z;
    const float fx = (float)(pix & (NW-1));
    const float fy = (float)(pix >> 7);

    const float d = depth_init[b*HW + pix] * scale_hypo[b*NSC + s];
    const float CX = (float)NW / (float)(NW-1);
    const float CY = (float)NH / (float)(NH-1);

    uint4* recp = g_rec + ((size_t)(b*NSC + s)*HW + pix)*2;

    #pragma unroll
    for (int vv = 0; vv < 2; vv++) {
        const float* P = g_proj[vv*NB + b];
        float m0 = P[0]*fx + P[1]*fy + P[2];
        float m1 = P[3]*fx + P[4]*fy + P[5];
        float m2 = P[6]*fx + P[7]*fy + P[8];
        float px = fmaf(m0, d, P[9]);
        float py = fmaf(m1, d, P[10]);
        float pz = fmaf(m2, d, P[11]);
        float rz = __fdividef(1.0f, pz);
        float ix = fmaf(px*rz, CX, -0.5f);
        float iy = fmaf(py*rz, CY, -0.5f);
        ix = fminf(fmaxf(ix, -1.0f), (float)NW);
        iy = fminf(fmaxf(iy, -1.0f), (float)NH);
        float x0f = floorf(ix), y0f = floorf(iy);
        float wx1 = ix - x0f, wx0 = 1.0f - wx1;
        float wy1 = iy - y0f, wy0 = 1.0f - wy1;
        int x0p = (int)x0f + 1;
        int y0p = (int)y0f + 1;
        uint4 rec;
        rec.x = (unsigned)((y0p*PW + x0p) << 3);
        rec.y = packh2(__float2half_rn(wx0*wy0), __float2half_rn(wx1*wy0));
        rec.z = packh2(__float2half_rn(wx0*wy1), __float2half_rn(wx1*wy1));
        rec.w = 0;
        recp[vv] = rec;
    }
}

// ---------------------------------------------------------------------------
// Main gather kernel. 128 threads = 32 pixels x 4 lanes (16 channels each).
// 1024 blocks -> 6.92 blocks/SM, residency ~9 -> single balanced wave
// (skew 1.01 vs 1.16 at 512x256thr). Per-warp work identical to R15.
// ---------------------------------------------------------------------------
__global__ void __launch_bounds__(128) k_main() {
    const int b   = blockIdx.y;
    const int tid = threadIdx.x;
    const int w   = tid >> 5;               // warp 0..3
    const int l   = tid & 31;
    const int pgw = l >> 2;                 // pixel in warp 0..7
    const int cl  = l & 3;                  // channel chunk of 16
    const int pg  = (w << 3) | pgw;         // pixel in block 0..31
    const int pix = blockIdx.x * PIX_PER_BLK + pg;

    __shared__ float s_part[NSC][4];

    const uint4* f0 = (const uint4*)(g_f0h + (size_t)b*PP*(NC/2));
    const uint4* f1 = (const uint4*)(g_f8 + (size_t)(0*NB + b)*PP*NC) + cl;
    const uint4* f2 = (const uint4*)(g_f8 + (size_t)(1*NB + b)*PP*NC) + cl;

    // ref channels 16*cl .. 16*cl+15 (fp16, two uint4)
    __half2 r0h[8];
    {
        int pixp = ((pix >> 7) + 1)*PW + (pix & 127) + 1;
        uint4 qa = f0[(size_t)pixp*8 + cl*2];
        uint4 qb = f0[(size_t)pixp*8 + cl*2 + 1];
        r0h[0] = u2h2(qa.x); r0h[1] = u2h2(qa.y);
        r0h[2] = u2h2(qa.z); r0h[3] = u2h2(qa.w);
        r0h[4] = u2h2(qb.x); r0h[5] = u2h2(qb.y);
        r0h[6] = u2h2(qb.z); r0h[7] = u2h2(qb.w);
    }

    const uint4* rp = g_rec + ((size_t)(b*NSC + 0)*HW + pix)*2;
    uint4 ra = rp[0];
    uint4 rb = rp[1];

    #pragma unroll 1
    for (int s = 0; s < NSC; s++) {
        // prefetch next scale's records
        uint4 na, nb;
        if (s + 1 < NSC) {
            const uint4* np = rp + (size_t)2*HW;
            na = np[0];
            nb = np[1];
        }

        const __half2 zero = __float2half2_rn(0.0f);
        const int o1 = (int)(ra.x >> 1);   // uint4 units (4 per pixel)
        const int o2 = (int)(rb.x >> 1);
        __half2 w1lo = u2h2(ra.y);   // (w00, w01)
        __half2 w1hi = u2h2(ra.z);   // (w02, w03)
        __half2 w2lo = u2h2(rb.y);
        __half2 w2hi = u2h2(rb.z);

        // view 1 (4 taps x 16 channels)
        __half2 s1[8] = {zero, zero, zero, zero, zero, zero, zero, zero};
        ACC_TAP(f1, o1,               __low2half2(w1lo),  s1);
        ACC_TAP(f1, o1 + 4,           __high2half2(w1lo), s1);
        ACC_TAP(f1, o1 + (PW<<2),     __low2half2(w1hi),  s1);
        ACC_TAP(f1, o1 + (PW<<2) + 4, __high2half2(w1hi), s1);

        __half2 r1h[8];
        __half2 acc1h = zero;
        #pragma unroll
        for (int c = 0; c < 8; c++) {
            r1h[c] = __hsub2(r0h[c], s1[c]);
            acc1h = __hfma2(r1h[c], r1h[c], acc1h);
        }

        // view 2 (4 taps x 16 channels)
        __half2 s2[8] = {zero, zero, zero, zero, zero, zero, zero, zero};
        ACC_TAP(f2, o2,               __low2half2(w2lo),  s2);
        ACC_TAP(f2, o2 + 4,           __high2half2(w2lo), s2);
        ACC_TAP(f2, o2 + (PW<<2),     __low2half2(w2hi),  s2);
        ACC_TAP(f2, o2 + (PW<<2) + 4, __high2half2(w2hi), s2);

        __half2 acc2h = zero;
        #pragma unroll
        for (int c = 0; c < 8; c++) {
            __half2 r2 = __hsub2(r1h[c], s2[c]);
            acc2h = __hfma2(r2, r2, acc2h);
        }

        float2 a1 = __half22float2(acc1h);
        float2 a2 = __half22float2(acc2h);
        float acc1 = a1.x + a1.y;
        float acc2 = a2.x + a2.y;

        // reduce across 4 channel lanes
        #pragma unroll
        for (int o = 2; o > 0; o >>= 1) {
            acc1 += __shfl_xor_sync(0xffffffffu, acc1, o);
            acc2 += __shfl_xor_sync(0xffffffffu, acc2, o);
        }
        float cst = sqrtf(acc1) + sqrtf(acc2);
        // sum the warp's 8 pixels
        cst += __shfl_xor_sync(0xffffffffu, cst, 4);
        cst += __shfl_xor_sync(0xffffffffu, cst, 8);
        cst += __shfl_xor_sync(0xffffffffu, cst, 16);
        if (l == 0) s_part[s][w] = cst;

        ra = na; rb = nb;
        rp += (size_t)2*HW;
    }

    __syncthreads();
    if (tid < NSC) {
        float v = s_part[tid][0] + s_part[tid][1] + s_part[tid][2] + s_part[tid][3];
        g_partial[(b*NSC + tid)*GRIDX + blockIdx.x] = v;
    }
}

// ---------------------------------------------------------------------------
// Fused reduce + softmax. grid = NB, 1024 threads; 512 partials per scale.
// ---------------------------------------------------------------------------
__global__ void __launch_bounds__(1024) k_redfin(const float* __restrict__ scale_hypo,
                                                float* __restrict__ out) {
    const int b    = blockIdx.x;
    const int wid  = threadIdx.x >> 5;
    const int lane = threadIdx.x & 31;

    const float4* p = (const float4*)(g_partial + (b*NSC + wid)*GRIDX);
    float v = 0.0f;
    #pragma unroll
    for (int i = 0; i < 4; i++) {
        float4 t = p[lane + 32*i];
        v += t.x + t.y + t.z + t.w;
    }
    #pragma unroll
    for (int o = 16; o > 0; o >>= 1)
        v += __shfl_xor_sync(0xffffffffu, v, o);

    __shared__ float sc[NSC];
    if (lane == 0) sc[wid] = v * (1.0f / (2.0f * (float)HW));
    __syncthreads();

    if (wid == 0) {
        float cost = sc[lane];
        float m = cost;
        #pragma unroll
        for (int o = 16; o > 0; o >>= 1)
            m = fmaxf(m, __shfl_xor_sync(0xffffffffu, m, o));
        float e = expf(cost - m);
        float shp = scale_hypo[b*NSC + lane];
        float den = e, num = e * shp;
        #pragma unroll
        for (int o = 16; o > 0; o >>= 1) {
            den += __shfl_xor_sync(0xffffffffu, den, o);
            num += __shfl_xor_sync(0xffffffffu, num, o);
        }
        if (lane == 0) out[b] = num / den;
    }
}

extern "C" void kernel_launch(void* const* d_in, const int* in_sizes, int n_in,
                              void* d_out, int out_size) {
    const float* feat  = (const float*)d_in[0];
    const float* intr  = (const float*)d_in[1];
    const float* c2w   = (const float*)d_in[2];
    const float* scale = (const float*)d_in[3];
    const float* depth = (const float*)d_in[4];
    float* out = (float*)d_out;

    dim3 trg(HW/32, NV*NB);
    k_tr<<<trg, 256>>>(feat, intr, c2w);
    dim3 sg(HW/256, NSC, NB);
    k_setup<<<sg, 256>>>(scale, depth);
    dim3 grid(GRIDX, NB);
    k_main<<<grid, 128>>>();
    k_redfin<<<NB, 1024>>>(scale, out);
}

// round 17
// speedup vs baseline: 1.4940x; 1.0055x over previous
#include <cuda_runtime.h>
#include <cuda_fp16.h>
#include <cuda_fp8.h>
#include <math.h>

#define NV 3
#define NB 2
#define NC 64
#define NSC 32
#define NH 128
#define NW 128
#define HW (NH*NW)
#define PW 131                      // padded width  (1 left, 2 right)
#define PH 131                      // padded height (1 top, 2 bottom)
#define PP (PW*PH)
#define PIX_PER_BLK 32              // 128 threads = 32 pixels x 4 lanes
#define GRIDX (HW/PIX_PER_BLK)      // 512

// Allocation-free scratch (zero-initialized; padding rings stay 0).
__device__ float g_proj[(NV-1)*NB][12];
__device__ float g_partial[NB*NSC*GRIDX];
__device__ __align__(16) __half2 g_f0h[(size_t)NB*PP*(NC/2)];          // ref view fp16 padded
__device__ __align__(16) unsigned char g_f8[(size_t)(NV-1)*NB*PP*NC];  // views 1,2 fp8 padded
// Tap records: per (b,s,pix,view): {base_off(8-per-pixel units), pack(w0,w1), pack(w2,w3), 0}
__device__ __align__(16) uint4 g_rec[(size_t)NB*NSC*HW*2];

__device__ __forceinline__ void mat3mul(const float* A, const float* B, float* C) {
    #pragma unroll
    for (int i = 0; i < 3; i++)
        #pragma unroll
        for (int j = 0; j < 3; j++)
            C[i*3+j] = A[i*3+0]*B[0*3+j] + A[i*3+1]*B[1*3+j] + A[i*3+2]*B[2*3+j];
}
__device__ __forceinline__ void mat3vec(const float* A, const float* v, float* r) {
    #pragma unroll
    for (int i = 0; i < 3; i++)
        r[i] = A[i*3+0]*v[0] + A[i*3+1]*v[1] + A[i*3+2]*v[2];
}
__device__ __forceinline__ void mat3inv(const float* A, float* Ai) {
    float a=A[0],b=A[1],c=A[2],d=A[3],e=A[4],f=A[5],g=A[6],h=A[7],i=A[8];
    float det = a*(e*i-f*h) - b*(d*i-f*g) + c*(d*h-e*g);
    float inv = 1.0f / det;
    Ai[0] =  (e*i - f*h)*inv; Ai[1] = -(b*i - c*h)*inv; Ai[2] =  (b*f - c*e)*inv;
    Ai[3] = -(d*i - f*g)*inv; Ai[4] =  (a*i - c*g)*inv; Ai[5] = -(a*f - c*d)*inv;
    Ai[6] =  (d*h - e*g)*inv; Ai[7] = -(a*h - b*g)*inv; Ai[8] =  (a*e - b*d)*inv;
}
__device__ __forceinline__ __half2 u2h2(unsigned u) {
    return *reinterpret_cast<__half2*>(&u);
}
__device__ __forceinline__ unsigned packh2(__half a, __half b) {
    __half2 h = __halves2half2(a, b);
    return *reinterpret_cast<unsigned*>(&h);
}
__device__ __forceinline__ __half2 f8x2h2(unsigned short v) {
    __half2_raw r = __nv_cvt_fp8x2_to_halfraw2((__nv_fp8x2_storage_t)v, __NV_E4M3);
    return *reinterpret_cast<__half2*>(&r);
}

// Accumulate one fp8 tap (16 channels in uint4) into 8 half2 accumulators.
#define ACC_TAP(Fp, idx, ww, S) do {                                  \
    uint4 q = (Fp)[idx];                                              \
    S[0]=__hfma2(f8x2h2((unsigned short)q.x),        (ww), S[0]);     \
    S[1]=__hfma2(f8x2h2((unsigned short)(q.x>>16)),  (ww), S[1]);     \
    S[2]=__hfma2(f8x2h2((unsigned short)q.y),        (ww), S[2]);     \
    S[3]=__hfma2(f8x2h2((unsigned short)(q.y>>16)),  (ww), S[3]);     \
    S[4]=__hfma2(f8x2h2((unsigned short)q.z),        (ww), S[4]);     \
    S[5]=__hfma2(f8x2h2((unsigned short)(q.z>>16)),  (ww), S[5]);     \
    S[6]=__hfma2(f8x2h2((unsigned short)q.w),        (ww), S[6]);     \
    S[7]=__hfma2(f8x2h2((unsigned short)(q.w>>16)),  (ww), S[7]);     \
} while (0)

// ---------------------------------------------------------------------------
// Transpose (C,HW) -> padded (PH,PW,C); view0 fp16, views 1,2 fp8(e4m3).
// Homography prep fused into block (0,0). grid (HW/32, V*B), 256 threads.
// (R14/R15 verbatim — passing.)
// ---------------------------------------------------------------------------
__global__ void __launch_bounds__(256) k_tr(const float* __restrict__ feat,
                                            const float* __restrict__ intr,
                                            const float* __restrict__ c2w) {
    if (blockIdx.x == 0 && blockIdx.y == 0 && threadIdx.x < (NV-1)*NB) {
        int tid = threadIdx.x;
        int v = 1 + tid / NB;
        int b = tid % NB;
        const float* Kr = intr + (0*NB + b)*9;
        const float* Tr = c2w  + (0*NB + b)*16;
        const float* Ks = intr + (v*NB + b)*9;
        const float* Ts = c2w  + (v*NB + b)*16;

        float RrT[9], RsT[9], tr[3], ts[3];
        #pragma unroll
        for (int i = 0; i < 3; i++) {
            #pragma unroll
            for (int j = 0; j < 3; j++) {
                RrT[j*3+i] = Tr[i*4+j];
                RsT[j*3+i] = Ts[i*4+j];
            }
            tr[i] = Tr[i*4+3];
            ts[i] = Ts[i*4+3];
        }
        float trw[3], tsw[3], tmp[3];
        mat3vec(RrT, tr, tmp); trw[0]=-tmp[0]; trw[1]=-tmp[1]; trw[2]=-tmp[2];
        mat3vec(RsT, ts, tmp); tsw[0]=-tmp[0]; tsw[1]=-tmp[1]; tsw[2]=-tmp[2];

        float A[9], bref[3], Ai[9];
        mat3mul(Kr, RrT, A);
        mat3vec(Kr, trw, tmp);
        bref[0]=tmp[0]+trw[0]; bref[1]=tmp[1]+trw[1]; bref[2]=tmp[2]+trw[2];
        mat3inv(A, Ai);

        float SM[9], St[3];
        mat3mul(Ks, RsT, SM);
        mat3vec(Ks, tsw, tmp);
        St[0]=tmp[0]+tsw[0]; St[1]=tmp[1]+tsw[1]; St[2]=tmp[2]+tsw[2];

        float M[9], Mb[3];
        mat3mul(SM, Ai, M);
        mat3vec(M, bref, Mb);

        float* o = g_proj[(v-1)*NB + b];
        #pragma unroll
        for (int i = 0; i < 9; i++) o[i] = M[i];
        o[9]  = St[0] - Mb[0];
        o[10] = St[1] - Mb[1];
        o[11] = St[2] - Mb[2];
    }

    __shared__ float t[NC][33];
    const int vb  = blockIdx.y;
    const int v   = vb >> 1;         // NB == 2
    const int b   = vb & 1;
    const int hw0 = blockIdx.x * 32;
    const int tid = threadIdx.x;
    const float* src = feat + (size_t)vb * NC * HW;

    #pragma unroll
    for (int i = tid; i < NC*8; i += 256) {
        int c = i >> 3, j4 = (i & 7) << 2;
        float4 v4 = *(const float4*)(src + (size_t)c * HW + hw0 + j4);
        t[c][j4+0] = v4.x; t[c][j4+1] = v4.y; t[c][j4+2] = v4.z; t[c][j4+3] = v4.w;
    }
    __syncthreads();

    {
        int pg = tid >> 3;           // pixel 0..31
        int g8 = tid & 7;            // channel-group of 8
        int g  = hw0 + pg;
        int y  = g >> 7, x = g & 127;
        size_t ppix = (size_t)((y+1)*PW + (x+1));

        if (v == 0) {
            uint4 o4;
            unsigned* op = &o4.x;
            #pragma unroll
            for (int k = 0; k < 4; k++) {
                __half2 h = __floats2half2_rn(t[g8*8 + 2*k][pg], t[g8*8 + 2*k + 1][pg]);
                op[k] = *reinterpret_cast<unsigned*>(&h);
            }
            uint4* dst = (uint4*)(g_f0h + (size_t)b * PP * (NC/2));
            dst[ppix * 8 + g8] = o4;
        } else {
            unsigned short s0 = __nv_cvt_float2_to_fp8x2(
                make_float2(t[g8*8+0][pg], t[g8*8+1][pg]), __NV_SATFINITE, __NV_E4M3);
            unsigned short s1 = __nv_cvt_float2_to_fp8x2(
                make_float2(t[g8*8+2][pg], t[g8*8+3][pg]), __NV_SATFINITE, __NV_E4M3);
            unsigned short s2 = __nv_cvt_float2_to_fp8x2(
                make_float2(t[g8*8+4][pg], t[g8*8+5][pg]), __NV_SATFINITE, __NV_E4M3);
            unsigned short s3 = __nv_cvt_float2_to_fp8x2(
                make_float2(t[g8*8+6][pg], t[g8*8+7][pg]), __NV_SATFINITE, __NV_E4M3);
            uint2 o2v;
            o2v.x = (unsigned)s0 | ((unsigned)s1 << 16);
            o2v.y = (unsigned)s2 | ((unsigned)s3 << 16);
            uint2* dst = (uint2*)(g_f8 + (size_t)((v-1)*NB + b) * PP * NC);
            dst[ppix * 8 + g8] = o2v;
        }
    }
}

// ---------------------------------------------------------------------------
// Tap-record precompute (verbatim). grid (HW/256, NSC, NB).
// ---------------------------------------------------------------------------
__global__ void __launch_bounds__(256) k_setup(const float* __restrict__ scale_hypo,
                                              const float* __restrict__ depth_init) {
    const int pix = blockIdx.x * 256 + threadIdx.x;
    const int s   = blockIdx.y;
    const int b   = blockIdx.z;
    const float fx = (float)(pix & (NW-1));
    const float fy = (float)(pix >> 7);

    const float d = depth_init[b*HW + pix] * scale_hypo[b*NSC + s];
    const float CX = (float)NW / (float)(NW-1);
    const float CY = (float)NH / (float)(NH-1);

    uint4* recp = g_rec + ((size_t)(b*NSC + s)*HW + pix)*2;

    #pragma unroll
    for (int vv = 0; vv < 2; vv++) {
        const float* P = g_proj[vv*NB + b];
        float m0 = P[0]*fx + P[1]*fy + P[2];
        float m1 = P[3]*fx + P[4]*fy + P[5];
        float m2 = P[6]*fx + P[7]*fy + P[8];
        float px = fmaf(m0, d, P[9]);
        float py = fmaf(m1, d, P[10]);
        float pz = fmaf(m2, d, P[11]);
        float rz = __fdividef(1.0f, pz);
        float ix = fmaf(px*rz, CX, -0.5f);
        float iy = fmaf(py*rz, CY, -0.5f);
        ix = fminf(fmaxf(ix, -1.0f), (float)NW);
        iy = fminf(fmaxf(iy, -1.0f), (float)NH);
        float x0f = floorf(ix), y0f = floorf(iy);
        float wx1 = ix - x0f, wx0 = 1.0f - wx1;
        float wy1 = iy - y0f, wy0 = 1.0f - wy1;
        int x0p = (int)x0f + 1;
        int y0p = (int)y0f + 1;
        uint4 rec;
        rec.x = (unsigned)((y0p*PW + x0p) << 3);
        rec.y = packh2(__float2half_rn(wx0*wy0), __float2half_rn(wx1*wy0));
        rec.z = packh2(__float2half_rn(wx0*wy1), __float2half_rn(wx1*wy1));
        rec.w = 0;
        recp[vv] = rec;
    }
}

// ---------------------------------------------------------------------------
// Main gather kernel. 128 threads = 32 pixels x 4 lanes (16 channels each).
// 1024 blocks -> 6.92 blocks/SM, residency ~9 -> single balanced wave
// (skew 1.01 vs 1.16 at 512x256thr). Per-warp work identical to R15.
// ---------------------------------------------------------------------------
__global__ void __launch_bounds__(128) k_main() {
    const int b   = blockIdx.y;
    const int tid = threadIdx.x;
    const int w   = tid >> 5;               // warp 0..3
    const int l   = tid & 31;
    const int pgw = l >> 2;                 // pixel in warp 0..7
    const int cl  = l & 3;                  // channel chunk of 16
    const int pg  = (w << 3) | pgw;         // pixel in block 0..31
    const int pix = blockIdx.x * PIX_PER_BLK + pg;

    __shared__ float s_part[NSC][4];

    const uint4* f0 = (const uint4*)(g_f0h + (size_t)b*PP*(NC/2));
    const uint4* f1 = (const uint4*)(g_f8 + (size_t)(0*NB + b)*PP*NC) + cl;
    const uint4* f2 = (const uint4*)(g_f8 + (size_t)(1*NB + b)*PP*NC) + cl;

    // ref channels 16*cl .. 16*cl+15 (fp16, two uint4)
    __half2 r0h[8];
    {
        int pixp = ((pix >> 7) + 1)*PW + (pix & 127) + 1;
        uint4 qa = f0[(size_t)pixp*8 + cl*2];
        uint4 qb = f0[(size_t)pixp*8 + cl*2 + 1];
        r0h[0] = u2h2(qa.x); r0h[1] = u2h2(qa.y);
        r0h[2] = u2h2(qa.z); r0h[3] = u2h2(qa.w);
        r0h[4] = u2h2(qb.x); r0h[5] = u2h2(qb.y);
        r0h[6] = u2h2(qb.z); r0h[7] = u2h2(qb.w);
    }

    const uint4* rp = g_rec + ((size_t)(b*NSC + 0)*HW + pix)*2;
    uint4 ra = rp[0];
    uint4 rb = rp[1];

    #pragma unroll 1
    for (int s = 0; s < NSC; s++) {
        // prefetch next scale's records
        uint4 na, nb;
        if (s + 1 < NSC) {
            const uint4* np = rp + (size_t)2*HW;
            na = np[0];
            nb = np[1];
        }

        const __half2 zero = __float2half2_rn(0.0f);
        const int o1 = (int)(ra.x >> 1);   // uint4 units (4 per pixel)
        const int o2 = (int)(rb.x >> 1);
        __half2 w1lo = u2h2(ra.y);   // (w00, w01)
        __half2 w1hi = u2h2(ra.z);   // (w02, w03)
        __half2 w2lo = u2h2(rb.y);
        __half2 w2hi = u2h2(rb.z);

        // view 1 (4 taps x 16 channels)
        __half2 s1[8] = {zero, zero, zero, zero, zero, zero, zero, zero};
        ACC_TAP(f1, o1,               __low2half2(w1lo),  s1);
        ACC_TAP(f1, o1 + 4,           __high2half2(w1lo), s1);
        ACC_TAP(f1, o1 + (PW<<2),     __low2half2(w1hi),  s1);
        ACC_TAP(f1, o1 + (PW<<2) + 4, __high2half2(w1hi), s1);

        __half2 r1h[8];
        __half2 acc1h = zero;
        #pragma unroll
        for (int c = 0; c < 8; c++) {
            r1h[c] = __hsub2(r0h[c], s1[c]);
            acc1h = __hfma2(r1h[c], r1h[c], acc1h);
        }

        // view 2 (4 taps x 16 channels)
        __half2 s2[8] = {zero, zero, zero, zero, zero, zero, zero, zero};
        ACC_TAP(f2, o2,               __low2half2(w2lo),  s2);
        ACC_TAP(f2, o2 + 4,           __high2half2(w2lo), s2);
        ACC_TAP(f2, o2 + (PW<<2),     __low2half2(w2hi),  s2);
        ACC_TAP(f2, o2 + (PW<<2) + 4, __high2half2(w2hi), s2);

        __half2 acc2h = zero;
        #pragma unroll
        for (int c = 0; c < 8; c++) {
            __half2 r2 = __hsub2(r1h[c], s2[c]);
            acc2h = __hfma2(r2, r2, acc2h);
        }

        float2 a1 = __half22float2(acc1h);
        float2 a2 = __half22float2(acc2h);
        float acc1 = a1.x + a1.y;
        float acc2 = a2.x + a2.y;

        // reduce across 4 channel lanes
        #pragma unroll
        for (int o = 2; o > 0; o >>= 1) {
            acc1 += __shfl_xor_sync(0xffffffffu, acc1, o);
            acc2 += __shfl_xor_sync(0xffffffffu, acc2, o);
        }
        float cst = sqrtf(acc1) + sqrtf(acc2);
        // sum the warp's 8 pixels
        cst += __shfl_xor_sync(0xffffffffu, cst, 4);
        cst += __shfl_xor_sync(0xffffffffu, cst, 8);
        cst += __shfl_xor_sync(0xffffffffu, cst, 16);
        if (l == 0) s_part[s][w] = cst;

        ra = na; rb = nb;
        rp += (size_t)2*HW;
    }

    __syncthreads();
    if (tid < NSC) {
        float v = s_part[tid][0] + s_part[tid][1] + s_part[tid][2] + s_part[tid][3];
        g_partial[(b*NSC + tid)*GRIDX + blockIdx.x] = v;
    }
}

// ---------------------------------------------------------------------------
// Fused reduce + softmax. grid = NB, 1024 threads; 512 partials per scale.
// ---------------------------------------------------------------------------
__global__ void __launch_bounds__(1024) k_redfin(const float* __restrict__ scale_hypo,
                                                float* __restrict__ out) {
    const int b    = blockIdx.x;
    const int wid  = threadIdx.x >> 5;
    const int lane = threadIdx.x & 31;

    const float4* p = (const float4*)(g_partial + (b*NSC + wid)*GRIDX);
    float v = 0.0f;
    #pragma unroll
    for (int i = 0; i < 4; i++) {
        float4 t = p[lane + 32*i];
        v += t.x + t.y + t.z + t.w;
    }
    #pragma unroll
    for (int o = 16; o > 0; o >>= 1)
        v += __shfl_xor_sync(0xffffffffu, v, o);

    __shared__ float sc[NSC];
    if (lane == 0) sc[wid] = v * (1.0f / (2.0f * (float)HW));
    __syncthreads();

    if (wid == 0) {
        float cost = sc[lane];
        float m = cost;
        #pragma unroll
        for (int o = 16; o > 0; o >>= 1)
            m = fmaxf(m, __shfl_xor_sync(0xffffffffu, m, o));
        float e = expf(cost - m);
        float shp = scale_hypo[b*NSC + lane];
        float den = e, num = e * shp;
        #pragma unroll
        for (int o = 16; o > 0; o >>= 1) {
            den += __shfl_xor_sync(0xffffffffu, den, o);
            num += __shfl_xor_sync(0xffffffffu, num, o);
        }
        if (lane == 0) out[b] = num / den;
    }
}

extern "C" void kernel_launch(void* const* d_in, const int* in_sizes, int n_in,
                              void* d_out, int out_size) {
    const float* feat  = (const float*)d_in[0];
    const float* intr  = (const float*)d_in[1];
    const float* c2w   = (const float*)d_in[2];
    const float* scale = (const float*)d_in[3];
    const float* depth = (const float*)d_in[4];
    float* out = (float*)d_out;

    dim3 trg(HW/32, NV*NB);
    k_tr<<<trg, 256>>>(feat, intr, c2w);
    dim3 sg(HW/256, NSC, NB);
    k_setup<<<sg, 256>>>(scale, depth);
    dim3 grid(GRIDX, NB);
    k_main<<<grid, 128>>>();
    k_redfin<<<NB, 1024>>>(scale, out);
}